// round 2
// baseline (speedup 1.0000x reference)
#include <cuda_runtime.h>
#include <math.h>

// ---------------------------------------------------------------------------
// Problem constants
// ---------------------------------------------------------------------------
#define BATCH   2
#define HH      256
#define WW_     256
#define CC      256
#define WS      8
#define NTOK    64          // tokens per window
#define NF      66          // spectral rows (33 real + 33 imag)
#define HEADS   8
#define HD      32
#define NWIN    2048        // B * (H/WS) * (W/WS) = 2*32*32
#define TOKS    131072      // B*H*W
#define TOKF    135168      // NWIN * NF
#define SCALE   0.17677669529663687f   // 32^-0.5

// ---------------------------------------------------------------------------
// Scratch (static device globals; no allocation at runtime)
// ---------------------------------------------------------------------------
__device__ float g_xln [ (size_t)NWIN * NTOK * CC ];          // LN1 output, windowed order
__device__ float g_qkvs[ (size_t)NWIN * NTOK * 3 * CC ];      // spatial qkv
__device__ float g_xf  [ (size_t)NWIN * NF   * CC ];          // rfft(xln)
__device__ float g_qkvf[ (size_t)NWIN * NF   * 3 * CC ];      // spectral qkv
__device__ float g_attn[ (size_t)NWIN * NTOK * CC ];          // spatial attn out (+= xr)
__device__ float g_outf[ (size_t)NWIN * NF   * CC ];          // spectral attn out
__device__ float g_x2  [ (size_t)TOKS * CC ];                 // after proj + shortcut
__device__ float g_hln [ (size_t)TOKS * CC ];                 // LN2 output
__device__ float g_h1  [ (size_t)TOKS * 4 * CC ];             // fc1+gelu output
__device__ float g_dftF[ NF * NTOK ];                         // forward DFT (66 x 64)
__device__ float g_dftI[ NTOK * NF ];                         // inverse DFT (64 x 66)

// ---------------------------------------------------------------------------
// DFT matrix init (re-run each launch; deterministic)
// ---------------------------------------------------------------------------
__global__ void init_dft_kernel() {
    int i = blockIdx.x * blockDim.x + threadIdx.x;
    if (i < NF * NTOK) {
        int f = i / NTOK, n = i % NTOK;
        float v;
        if (f < 33) v =  cospif((float)(f * n) / 32.0f);
        else        v = -sinpif((float)((f - 33) * n) / 32.0f);
        g_dftF[i] = v * 0.125f;                // 1/sqrt(64)
    }
    if (i < NTOK * NF) {
        int n = i / NF, r = i % NF;
        float v;
        if (r == 0)        v = 1.0f;
        else if (r < 32)   v =  2.0f * cospif((float)(r * n) / 32.0f);
        else if (r == 32)  v =  cospif((float)n);           // (-1)^n
        else if (r == 33 || r == 65) v = 0.0f;              // imag of DC/Nyquist dropped
        else               v = -2.0f * sinpif((float)((r - 33) * n) / 32.0f);
        g_dftI[i] = v * 0.125f;
    }
}

// ---------------------------------------------------------------------------
// windowed-token-index -> pixel-row-index mapping
// ---------------------------------------------------------------------------
__device__ __forceinline__ int win2pix(int t) {
    int b   = t >> 16;          // 65536 tokens per batch image
    int rem = t & 65535;
    int wl  = rem >> 6;         // window index within image (0..1023)
    int n   = rem & 63;         // token within window
    int wh  = wl >> 5, ww = wl & 31;
    int i   = n >> 3,  j  = n & 7;
    return (b * 256 + wh * 8 + i) * 256 + (ww * 8 + j);
}

// ---------------------------------------------------------------------------
// LayerNorm; winmap=1: read from pixel order, write windowed order (LN1)
//            winmap=0: plain row order (LN2)
// ---------------------------------------------------------------------------
__global__ void ln_kernel(const float* __restrict__ xin,
                          const float* __restrict__ w,
                          const float* __restrict__ b,
                          float* __restrict__ out, int winmap) {
    __shared__ float red[16];
    int t = blockIdx.x, c = threadIdx.x;
    int rin = winmap ? win2pix(t) : t;
    float v = xin[(size_t)rin * CC + c];
    float s = v, sq = v * v;
    #pragma unroll
    for (int o = 16; o; o >>= 1) {
        s  += __shfl_down_sync(0xffffffffu, s,  o);
        sq += __shfl_down_sync(0xffffffffu, sq, o);
    }
    int warp = c >> 5, lane = c & 31;
    if (lane == 0) { red[warp] = s; red[8 + warp] = sq; }
    __syncthreads();
    if (c == 0) {
        float S = 0.f, Q = 0.f;
        #pragma unroll
        for (int i = 0; i < 8; i++) { S += red[i]; Q += red[8 + i]; }
        red[0] = S * (1.0f / CC);
        red[8] = Q * (1.0f / CC);
    }
    __syncthreads();
    float mean = red[0];
    float var  = red[8] - mean * mean;
    out[(size_t)t * CC + c] = (v - mean) * rsqrtf(var + 1e-5f) * w[c] + b[c];
}

// ---------------------------------------------------------------------------
// Generic fp32 GEMM: C[M,N] = A[M,K] @ W[N,K]^T + bias[N]  (+ epilogue)
// 128x128 tiles, 8-deep K slices, 8x8 per thread, 256 threads.
// EPI: 0 plain, 1 GELU, 2 +res[m*N+n], 3 window-reverse: out[pix*N+n]=v+res[pix*N+n]
// ---------------------------------------------------------------------------
template<int EPI>
__global__ __launch_bounds__(256)
void gemm_kernel(const float* __restrict__ A, const float* __restrict__ W,
                 const float* __restrict__ bias, float* __restrict__ C,
                 int M, int N, int K, const float* __restrict__ res) {
    __shared__ float As[8][128];
    __shared__ float Bs[8][128];
    int tid = threadIdx.x;
    int tx = tid & 15, ty = tid >> 4;
    int m0 = blockIdx.y * 128, n0 = blockIdx.x * 128;
    int lrow = tid >> 1;
    int lk   = (tid & 1) * 4;
    const float* Aptr = A + (size_t)(m0 + lrow) * K + lk;
    const float* Wptr = W + (size_t)(n0 + lrow) * K + lk;

    float acc[8][8];
    #pragma unroll
    for (int i = 0; i < 8; i++)
        #pragma unroll
        for (int j = 0; j < 8; j++) acc[i][j] = 0.f;

    for (int k0 = 0; k0 < K; k0 += 8) {
        float4 av = *(const float4*)(Aptr + k0);
        float4 bv = *(const float4*)(Wptr + k0);
        __syncthreads();
        As[lk + 0][lrow] = av.x; As[lk + 1][lrow] = av.y;
        As[lk + 2][lrow] = av.z; As[lk + 3][lrow] = av.w;
        Bs[lk + 0][lrow] = bv.x; Bs[lk + 1][lrow] = bv.y;
        Bs[lk + 2][lrow] = bv.z; Bs[lk + 3][lrow] = bv.w;
        __syncthreads();
        #pragma unroll
        for (int kk = 0; kk < 8; kk++) {
            const float4* Ap = (const float4*)&As[kk][ty * 8];
            const float4* Bp = (const float4*)&Bs[kk][tx * 8];
            float4 a0 = Ap[0], a1 = Ap[1];
            float4 b0 = Bp[0], b1 = Bp[1];
            float a[8] = {a0.x, a0.y, a0.z, a0.w, a1.x, a1.y, a1.z, a1.w};
            float b[8] = {b0.x, b0.y, b0.z, b0.w, b1.x, b1.y, b1.z, b1.w};
            #pragma unroll
            for (int i = 0; i < 8; i++)
                #pragma unroll
                for (int j = 0; j < 8; j++)
                    acc[i][j] += a[i] * b[j];
        }
    }

    #pragma unroll
    for (int i = 0; i < 8; i++) {
        int m = m0 + ty * 8 + i;
        size_t orow;
        if (EPI == 3) orow = (size_t)win2pix(m) * N;
        else          orow = (size_t)m * N;
        #pragma unroll
        for (int j = 0; j < 8; j++) {
            int n = n0 + tx * 8 + j;
            float v = acc[i][j] + bias[n];
            if (EPI == 1) {
                v = 0.5f * v * (1.0f + erff(v * 0.7071067811865476f));
            } else if (EPI == 2) {
                v += res[(size_t)m * N + n];
            } else if (EPI == 3) {
                v += res[orow + n];
            }
            C[orow + n] = v;
        }
    }
}

// ---------------------------------------------------------------------------
// Window attention. NT tokens, one thread per row. BIAS: rel-pos bias (spatial).
// qkv layout: [(w*NT + tok) * 768 + which*256 + head*32 + d]
// out layout: [(w*NT + tok) * 256 + head*32 + d]
// ---------------------------------------------------------------------------
template<int NT, bool BIAS>
__global__ void attn_kernel(const float* __restrict__ qkv,
                            const float* __restrict__ rpb,
                            float* __restrict__ outp) {
    __shared__ float qs[NT][33];
    __shared__ float ks[NT][33];
    __shared__ float vs[NT][33];
    __shared__ float ss[NT][NT + 1];
    __shared__ float rpb_s[BIAS ? 225 : 1];

    int w = blockIdx.x, h = blockIdx.y;
    int row = threadIdx.x;

    {
        size_t base = ((size_t)w * NT + row) * 768 + h * 32;
        #pragma unroll
        for (int d = 0; d < HD; d++) {
            qs[row][d] = qkv[base + d];
            ks[row][d] = qkv[base + 256 + d];
            vs[row][d] = qkv[base + 512 + d];
        }
    }
    if (BIAS) {
        for (int m = row; m < 225; m += NT) rpb_s[m] = rpb[m * HEADS + h];
    }
    __syncthreads();

    float qr[HD];
    #pragma unroll
    for (int d = 0; d < HD; d++) qr[d] = qs[row][d];

    float mx = -1e30f;
    int yi = row >> 3, xi = row & 7;
    for (int j = 0; j < NT; j++) {
        float s = 0.f;
        #pragma unroll
        for (int d = 0; d < HD; d++) s += qr[d] * ks[j][d];
        s *= SCALE;
        if (BIAS) {
            int yj = j >> 3, xj = j & 7;
            int idx = (yi - yj + 7) * 15 + (xi - xj + 7);
            s += rpb_s[idx];
        }
        ss[row][j] = s;
        mx = fmaxf(mx, s);
    }
    float sum = 0.f;
    for (int j = 0; j < NT; j++) {
        float e = expf(ss[row][j] - mx);
        ss[row][j] = e;
        sum += e;
    }
    float inv = 1.0f / sum;

    float acc[HD];
    #pragma unroll
    for (int d = 0; d < HD; d++) acc[d] = 0.f;
    for (int j = 0; j < NT; j++) {
        float p = ss[row][j];
        #pragma unroll
        for (int d = 0; d < HD; d++) acc[d] += p * vs[j][d];
    }
    size_t obase = ((size_t)w * NT + row) * CC + h * 32;
    #pragma unroll
    for (int d = 0; d < HD; d++) outp[obase + d] = acc[d] * inv;
}

// ---------------------------------------------------------------------------
// Forward rfft (ortho) as 66x64 matmul per window, 64-channel chunks.
// ---------------------------------------------------------------------------
__global__ void fft_fwd_kernel(const float* __restrict__ xin,
                               float* __restrict__ xf) {
    __shared__ float xs[NTOK][65];
    __shared__ float Ws[NF][NTOK];
    int w = blockIdx.x;
    int tid = threadIdx.x;
    for (int m = tid; m < NF * NTOK; m += 256) Ws[m / NTOK][m % NTOK] = g_dftF[m];
    int c  = tid & 63;
    int f0 = tid >> 6;
    for (int chunk = 0; chunk < 4; chunk++) {
        __syncthreads();
        for (int m = tid; m < NTOK * 64; m += 256) {
            int n = m >> 6, cc = m & 63;
            xs[n][cc] = xin[((size_t)w * NTOK + n) * CC + chunk * 64 + cc];
        }
        __syncthreads();
        for (int f = f0; f < NF; f += 4) {
            float s = 0.f;
            #pragma unroll 16
            for (int n = 0; n < NTOK; n++) s += Ws[f][n] * xs[n][c];
            xf[((size_t)w * NF + f) * CC + chunk * 64 + c] = s;
        }
    }
}

// ---------------------------------------------------------------------------
// Inverse rfft (ortho) as 64x66 matmul; accumulates into g_attn (+=).
// Safe under graph replay: g_attn is fully re-written by attn_kernel first.
// ---------------------------------------------------------------------------
__global__ void fft_inv_kernel(const float* __restrict__ outf,
                               float* __restrict__ acc) {
    __shared__ float fs[NF][65];
    __shared__ float Ws[NTOK][NF];
    int w = blockIdx.x;
    int tid = threadIdx.x;
    for (int m = tid; m < NTOK * NF; m += 256) Ws[m / NF][m % NF] = g_dftI[m];
    int c  = tid & 63;
    int n0 = tid >> 6;
    for (int chunk = 0; chunk < 4; chunk++) {
        __syncthreads();
        for (int m = tid; m < NF * 64; m += 256) {
            int r = m >> 6, cc = m & 63;
            fs[r][cc] = outf[((size_t)w * NF + r) * CC + chunk * 64 + cc];
        }
        __syncthreads();
        for (int n = n0; n < NTOK; n += 4) {
            float s = 0.f;
            #pragma unroll 11
            for (int r = 0; r < NF; r++) s += Ws[n][r] * fs[r][c];
            acc[((size_t)w * NTOK + n) * CC + chunk * 64 + c] += s;
        }
    }
}

// ---------------------------------------------------------------------------
// Launch
// ---------------------------------------------------------------------------
extern "C" void kernel_launch(void* const* d_in, const int* in_sizes, int n_in,
                              void* d_out, int out_size) {
    (void)in_sizes; (void)n_in; (void)out_size;
    const float* x     = (const float*)d_in[0];
    const float* n1w   = (const float*)d_in[2];
    const float* n1b   = (const float*)d_in[3];
    const float* qkvw  = (const float*)d_in[4];
    const float* qkvb  = (const float*)d_in[5];
    const float* rpb   = (const float*)d_in[6];
    const float* projw = (const float*)d_in[7];
    const float* projb = (const float*)d_in[8];
    const float* n2w   = (const float*)d_in[9];
    const float* n2b   = (const float*)d_in[10];
    const float* fc1w  = (const float*)d_in[11];
    const float* fc1b  = (const float*)d_in[12];
    const float* fc2w  = (const float*)d_in[13];
    const float* fc2b  = (const float*)d_in[14];
    float* out = (float*)d_out;

    float *xln, *qkvs, *xf, *qkvf, *attn, *outf, *x2, *hln, *h1;
    cudaGetSymbolAddress((void**)&xln,  g_xln);
    cudaGetSymbolAddress((void**)&qkvs, g_qkvs);
    cudaGetSymbolAddress((void**)&xf,   g_xf);
    cudaGetSymbolAddress((void**)&qkvf, g_qkvf);
    cudaGetSymbolAddress((void**)&attn, g_attn);
    cudaGetSymbolAddress((void**)&outf, g_outf);
    cudaGetSymbolAddress((void**)&x2,   g_x2);
    cudaGetSymbolAddress((void**)&hln,  g_hln);
    cudaGetSymbolAddress((void**)&h1,   g_h1);

    init_dft_kernel<<<17, 256>>>();

    // LN1 (+ window partition)
    ln_kernel<<<TOKS, 256>>>(x, n1w, n1b, xln, 1);

    // spatial qkv: (131072 x 768) = xln (131072 x 256) @ qkv_w^T
    gemm_kernel<0><<<dim3(768 / 128, TOKS / 128), 256>>>(
        xln, qkvw, qkvb, qkvs, TOKS, 768, 256, nullptr);

    // spectral input
    fft_fwd_kernel<<<NWIN, 256>>>(xln, xf);

    // spectral qkv: (135168 x 768)
    gemm_kernel<0><<<dim3(768 / 128, TOKF / 128), 256>>>(
        xf, qkvw, qkvb, qkvf, TOKF, 768, 256, nullptr);

    // attention
    attn_kernel<NTOK, true ><<<dim3(NWIN, HEADS), NTOK>>>(qkvs, rpb, attn);
    attn_kernel<NF,   false><<<dim3(NWIN, HEADS), NF  >>>(qkvf, nullptr, outf);

    // irfft of spectral branch, accumulate into spatial attn output
    fft_inv_kernel<<<NWIN, 256>>>(outf, attn);

    // proj + window reverse + shortcut -> x2
    gemm_kernel<3><<<dim3(256 / 128, TOKS / 128), 256>>>(
        attn, projw, projb, x2, TOKS, 256, 256, x);

    // LN2
    ln_kernel<<<TOKS, 256>>>(x2, n2w, n2b, hln, 0);

    // fc1 + GELU
    gemm_kernel<1><<<dim3(1024 / 128, TOKS / 128), 256>>>(
        hln, fc1w, fc1b, h1, TOKS, 1024, 256, nullptr);

    // fc2 + residual -> out
    gemm_kernel<2><<<dim3(256 / 128, TOKS / 128), 256>>>(
        h1, fc2w, fc2b, out, TOKS, 256, 1024, x2);
}

// round 4
// speedup vs baseline: 1.8179x; 1.8179x over previous
#include <cuda_runtime.h>
#include <math.h>
#include <stdint.h>

// ---------------------------------------------------------------------------
// Problem constants
// ---------------------------------------------------------------------------
#define CC      256
#define WS      8
#define NTOK    64
#define NF      66
#define HEADS   8
#define HD      32
#define NWIN    2048
#define TOKS    131072
#define TOKF    135168
#define SCALE   0.17677669529663687f

// ---------------------------------------------------------------------------
// Scratch
// ---------------------------------------------------------------------------
__device__ float g_xln [ (size_t)NWIN * NTOK * CC ];
__device__ float g_qkvs[ (size_t)NWIN * NTOK * 3 * CC ];
__device__ float g_xf  [ (size_t)NWIN * NF   * CC ];
__device__ float g_qkvf[ (size_t)NWIN * NF   * 3 * CC ];
__device__ float g_attn[ (size_t)NWIN * NTOK * CC ];
__device__ float g_outf[ (size_t)NWIN * NF   * CC ];
__device__ float g_x2  [ (size_t)TOKS * CC ];
__device__ float g_hln [ (size_t)TOKS * CC ];
__device__ float g_h1  [ (size_t)TOKS * 4 * CC ];
__device__ float g_dftF[ NF * NTOK ];
__device__ float g_dftI[ NTOK * NF ];

// ---------------------------------------------------------------------------
// Helpers
// ---------------------------------------------------------------------------
__device__ __forceinline__ uint32_t smem_u32(const void* p) {
    uint32_t a;
    asm("{ .reg .u64 t; cvta.to.shared.u64 t, %1; cvt.u32.u64 %0, t; }"
        : "=r"(a) : "l"(p));
    return a;
}

#define CP_ASYNC16(dst_u32, src_ptr) \
    asm volatile("cp.async.cg.shared.global [%0], [%1], 16;" \
        :: "r"(dst_u32), "l"(src_ptr))
#define CP_COMMIT() asm volatile("cp.async.commit_group;")
#define CP_WAIT1()  asm volatile("cp.async.wait_group 1;")
#define CP_WAIT0()  asm volatile("cp.async.wait_group 0;")

__device__ __forceinline__ void mma16n8k8(float* c, const uint32_t* a,
                                          const uint32_t* b) {
    asm volatile(
        "mma.sync.aligned.m16n8k8.row.col.f32.tf32.tf32.f32 "
        "{%0,%1,%2,%3}, {%4,%5,%6,%7}, {%8,%9}, {%0,%1,%2,%3};"
        : "+f"(c[0]), "+f"(c[1]), "+f"(c[2]), "+f"(c[3])
        : "r"(a[0]), "r"(a[1]), "r"(a[2]), "r"(a[3]), "r"(b[0]), "r"(b[1]));
}

__device__ __forceinline__ int win2pix(int t) {
    int b   = t >> 16;
    int rem = t & 65535;
    int wl  = rem >> 6;
    int n   = rem & 63;
    int wh  = wl >> 5, ww = wl & 31;
    int i   = n >> 3,  j  = n & 7;
    return (b * 256 + wh * 8 + i) * 256 + (ww * 8 + j);
}

// ---------------------------------------------------------------------------
// DFT matrix init
// ---------------------------------------------------------------------------
__global__ void init_dft_kernel() {
    int i = blockIdx.x * blockDim.x + threadIdx.x;
    if (i < NF * NTOK) {
        int f = i / NTOK, n = i % NTOK;
        float v;
        if (f < 33) v =  cospif((float)(f * n) / 32.0f);
        else        v = -sinpif((float)((f - 33) * n) / 32.0f);
        g_dftF[i] = v * 0.125f;
    }
    if (i < NTOK * NF) {
        int n = i / NF, r = i % NF;
        float v;
        if (r == 0)        v = 1.0f;
        else if (r < 32)   v =  2.0f * cospif((float)(r * n) / 32.0f);
        else if (r == 32)  v =  cospif((float)n);
        else if (r == 33 || r == 65) v = 0.0f;
        else               v = -2.0f * sinpif((float)((r - 33) * n) / 32.0f);
        g_dftI[i] = v * 0.125f;
    }
}

// ---------------------------------------------------------------------------
// LayerNorm
// ---------------------------------------------------------------------------
__global__ void ln_kernel(const float* __restrict__ xin,
                          const float* __restrict__ w,
                          const float* __restrict__ b,
                          float* __restrict__ out, int winmap) {
    __shared__ float red[16];
    int t = blockIdx.x, c = threadIdx.x;
    int rin = winmap ? win2pix(t) : t;
    float v = xin[(size_t)rin * CC + c];
    float s = v, sq = v * v;
    #pragma unroll
    for (int o = 16; o; o >>= 1) {
        s  += __shfl_down_sync(0xffffffffu, s,  o);
        sq += __shfl_down_sync(0xffffffffu, sq, o);
    }
    int warp = c >> 5, lane = c & 31;
    if (lane == 0) { red[warp] = s; red[8 + warp] = sq; }
    __syncthreads();
    if (c == 0) {
        float S = 0.f, Q = 0.f;
        #pragma unroll
        for (int i = 0; i < 8; i++) { S += red[i]; Q += red[8 + i]; }
        red[0] = S * (1.0f / CC);
        red[8] = Q * (1.0f / CC);
    }
    __syncthreads();
    float mean = red[0];
    float var  = red[8] - mean * mean;
    out[(size_t)t * CC + c] = (v - mean) * rsqrtf(var + 1e-5f) * w[c] + b[c];
}

// ---------------------------------------------------------------------------
// tf32 mma.sync GEMM: C[M,N] = A[M,K] @ W[N,K]^T + bias (+ epilogue)
// 128x128 CTA tile, BK=32, 8 warps (2x4), warp tile 64x32 (m16n8k8 frags).
// cp.async 2-stage pipeline. smem stride 36 floats (conflict-free frags,
// 16B-aligned rows).
// EPI: 0 plain, 1 GELU, 2 +res[m*N+n], 3 window-reverse +res
// ---------------------------------------------------------------------------
#define SMS 36                    // smem row stride in floats
#define STAGE (128 * SMS)         // floats per stage per operand
#define GEMM_SMEM (4 * STAGE * 4) // bytes: 2 ops x 2 stages

template<int EPI>
__global__ __launch_bounds__(256)
void gemm_mma(const float* __restrict__ A, const float* __restrict__ W,
              const float* __restrict__ bias, float* __restrict__ C,
              int M, int N, int K, const float* __restrict__ res) {
    extern __shared__ float sm[];
    float* AsBase = sm;                 // [2][128][SMS]
    float* BsBase = sm + 2 * STAGE;     // [2][128][SMS]
    uint32_t sA = smem_u32(AsBase);
    uint32_t sB = smem_u32(BsBase);

    int tid = threadIdx.x;
    int m0 = blockIdx.y * 128, n0 = blockIdx.x * 128;
    int wid = tid >> 5, lane = tid & 31;
    int wm = (wid & 1) * 64, wn = (wid >> 1) * 32;
    int grp = lane >> 2, tg = lane & 3;

    float acc[4][4][4];
    #pragma unroll
    for (int a = 0; a < 4; a++)
        #pragma unroll
        for (int b = 0; b < 4; b++)
            #pragma unroll
            for (int c = 0; c < 4; c++) acc[a][b][c] = 0.f;

    const int NC = K / 32;
    int grow = tid >> 1;              // 0..127
    int gq   = (tid & 1) * 4;         // 0 or 4 (float4 index); 2 float4 per row half
    // each thread loads 4 float4 for A and 4 for B per chunk:
    // idx = tid + t*256 -> row = idx>>3 (0..127), q = idx&7 (0..7)
    (void)grow; (void)gq;

    // prologue: chunk 0 -> stage 0
    #pragma unroll
    for (int t = 0; t < 4; t++) {
        int idx = tid + t * 256;
        int row = idx >> 3, q = idx & 7;
        CP_ASYNC16(sA + (uint32_t)(row * SMS + q * 4) * 4u,
                   A + (size_t)(m0 + row) * K + q * 4);
        CP_ASYNC16(sB + (uint32_t)(row * SMS + q * 4) * 4u,
                   W + (size_t)(n0 + row) * K + q * 4);
    }
    CP_COMMIT();

    for (int i = 0; i < NC; i++) {
        int s = i & 1;
        if (i + 1 < NC) {
            int s2 = s ^ 1;
            #pragma unroll
            for (int t = 0; t < 4; t++) {
                int idx = tid + t * 256;
                int row = idx >> 3, q = idx & 7;
                CP_ASYNC16(sA + (uint32_t)(s2 * STAGE + row * SMS + q * 4) * 4u,
                           A + (size_t)(m0 + row) * K + (i + 1) * 32 + q * 4);
                CP_ASYNC16(sB + (uint32_t)(s2 * STAGE + row * SMS + q * 4) * 4u,
                           W + (size_t)(n0 + row) * K + (i + 1) * 32 + q * 4);
            }
            CP_COMMIT();
            CP_WAIT1();
        } else {
            CP_WAIT0();
        }
        __syncthreads();

        const float* As = AsBase + s * STAGE;
        const float* Bs = BsBase + s * STAGE;
        #pragma unroll
        for (int ks = 0; ks < 4; ks++) {
            uint32_t af[4][4];
            uint32_t bf[4][2];
            #pragma unroll
            for (int mi = 0; mi < 4; mi++) {
                int r = wm + mi * 16 + grp;
                af[mi][0] = __float_as_uint(As[r * SMS + ks * 8 + tg]);
                af[mi][1] = __float_as_uint(As[(r + 8) * SMS + ks * 8 + tg]);
                af[mi][2] = __float_as_uint(As[r * SMS + ks * 8 + tg + 4]);
                af[mi][3] = __float_as_uint(As[(r + 8) * SMS + ks * 8 + tg + 4]);
            }
            #pragma unroll
            for (int ni = 0; ni < 4; ni++) {
                int r = wn + ni * 8 + grp;
                bf[ni][0] = __float_as_uint(Bs[r * SMS + ks * 8 + tg]);
                bf[ni][1] = __float_as_uint(Bs[r * SMS + ks * 8 + tg + 4]);
            }
            #pragma unroll
            for (int mi = 0; mi < 4; mi++)
                #pragma unroll
                for (int ni = 0; ni < 4; ni++)
                    mma16n8k8(acc[mi][ni], af[mi], bf[ni]);
        }
        __syncthreads();
    }

    // epilogue: float2 stores
    #pragma unroll
    for (int mi = 0; mi < 4; mi++) {
        #pragma unroll
        for (int half = 0; half < 2; half++) {
            int m = m0 + wm + mi * 16 + grp + half * 8;
            size_t orow = (EPI == 3) ? (size_t)win2pix(m) * N : (size_t)m * N;
            #pragma unroll
            for (int ni = 0; ni < 4; ni++) {
                int n = n0 + wn + ni * 8 + tg * 2;
                float vx = acc[mi][ni][half * 2 + 0] + bias[n];
                float vy = acc[mi][ni][half * 2 + 1] + bias[n + 1];
                if (EPI == 1) {
                    vx = 0.5f * vx * (1.0f + erff(vx * 0.7071067811865476f));
                    vy = 0.5f * vy * (1.0f + erff(vy * 0.7071067811865476f));
                } else if (EPI == 2) {
                    vx += res[(size_t)m * N + n];
                    vy += res[(size_t)m * N + n + 1];
                } else if (EPI == 3) {
                    vx += res[orow + n];
                    vy += res[orow + n + 1];
                }
                *(float2*)(C + orow + n) = make_float2(vx, vy);
            }
        }
    }
}

// ---------------------------------------------------------------------------
// Window attention
// ---------------------------------------------------------------------------
template<int NT, bool BIAS>
__global__ void attn_kernel(const float* __restrict__ qkv,
                            const float* __restrict__ rpb,
                            float* __restrict__ outp) {
    __shared__ float qs[NT][33];
    __shared__ float ks[NT][33];
    __shared__ float vs[NT][33];
    __shared__ float ss[NT][NT + 1];
    __shared__ float rpb_s[BIAS ? 225 : 1];

    int w = blockIdx.x, h = blockIdx.y;
    int row = threadIdx.x;

    {
        size_t base = ((size_t)w * NT + row) * 768 + h * 32;
        #pragma unroll
        for (int d = 0; d < HD; d++) {
            qs[row][d] = qkv[base + d];
            ks[row][d] = qkv[base + 256 + d];
            vs[row][d] = qkv[base + 512 + d];
        }
    }
    if (BIAS) {
        for (int m = row; m < 225; m += NT) rpb_s[m] = rpb[m * HEADS + h];
    }
    __syncthreads();

    float qr[HD];
    #pragma unroll
    for (int d = 0; d < HD; d++) qr[d] = qs[row][d];

    float mx = -1e30f;
    int yi = row >> 3, xi = row & 7;
    for (int j = 0; j < NT; j++) {
        float s = 0.f;
        #pragma unroll
        for (int d = 0; d < HD; d++) s += qr[d] * ks[j][d];
        s *= SCALE;
        if (BIAS) {
            int yj = j >> 3, xj = j & 7;
            int idx = (yi - yj + 7) * 15 + (xi - xj + 7);
            s += rpb_s[idx];
        }
        ss[row][j] = s;
        mx = fmaxf(mx, s);
    }
    float sum = 0.f;
    for (int j = 0; j < NT; j++) {
        float e = expf(ss[row][j] - mx);
        ss[row][j] = e;
        sum += e;
    }
    float inv = 1.0f / sum;

    float acc[HD];
    #pragma unroll
    for (int d = 0; d < HD; d++) acc[d] = 0.f;
    for (int j = 0; j < NT; j++) {
        float p = ss[row][j];
        #pragma unroll
        for (int d = 0; d < HD; d++) acc[d] += p * vs[j][d];
    }
    size_t obase = ((size_t)w * NT + row) * CC + h * 32;
    #pragma unroll
    for (int d = 0; d < HD; d++) outp[obase + d] = acc[d] * inv;
}

// ---------------------------------------------------------------------------
// Forward / inverse DFT kernels
// ---------------------------------------------------------------------------
__global__ void fft_fwd_kernel(const float* __restrict__ xin,
                               float* __restrict__ xf) {
    __shared__ float xs[NTOK][65];
    __shared__ float Ws[NF][NTOK];
    int w = blockIdx.x;
    int tid = threadIdx.x;
    for (int m = tid; m < NF * NTOK; m += 256) Ws[m / NTOK][m % NTOK] = g_dftF[m];
    int c  = tid & 63;
    int f0 = tid >> 6;
    for (int chunk = 0; chunk < 4; chunk++) {
        __syncthreads();
        for (int m = tid; m < NTOK * 64; m += 256) {
            int n = m >> 6, cc = m & 63;
            xs[n][cc] = xin[((size_t)w * NTOK + n) * CC + chunk * 64 + cc];
        }
        __syncthreads();
        for (int f = f0; f < NF; f += 4) {
            float s = 0.f;
            #pragma unroll 16
            for (int n = 0; n < NTOK; n++) s += Ws[f][n] * xs[n][c];
            xf[((size_t)w * NF + f) * CC + chunk * 64 + c] = s;
        }
    }
}

__global__ void fft_inv_kernel(const float* __restrict__ outf,
                               float* __restrict__ acc) {
    __shared__ float fs[NF][65];
    __shared__ float Ws[NTOK][NF];
    int w = blockIdx.x;
    int tid = threadIdx.x;
    for (int m = tid; m < NTOK * NF; m += 256) Ws[m / NF][m % NF] = g_dftI[m];
    int c  = tid & 63;
    int n0 = tid >> 6;
    for (int chunk = 0; chunk < 4; chunk++) {
        __syncthreads();
        for (int m = tid; m < NF * 64; m += 256) {
            int r = m >> 6, cc = m & 63;
            fs[r][cc] = outf[((size_t)w * NF + r) * CC + chunk * 64 + cc];
        }
        __syncthreads();
        for (int n = n0; n < NTOK; n += 4) {
            float s = 0.f;
            #pragma unroll 11
            for (int r = 0; r < NF; r++) s += Ws[n][r] * fs[r][c];
            acc[((size_t)w * NTOK + n) * CC + chunk * 64 + c] += s;
        }
    }
}

// ---------------------------------------------------------------------------
// Launch
// ---------------------------------------------------------------------------
extern "C" void kernel_launch(void* const* d_in, const int* in_sizes, int n_in,
                              void* d_out, int out_size) {
    (void)in_sizes; (void)n_in; (void)out_size;
    const float* x     = (const float*)d_in[0];
    const float* n1w   = (const float*)d_in[2];
    const float* n1b   = (const float*)d_in[3];
    const float* qkvw  = (const float*)d_in[4];
    const float* qkvb  = (const float*)d_in[5];
    const float* rpb   = (const float*)d_in[6];
    const float* projw = (const float*)d_in[7];
    const float* projb = (const float*)d_in[8];
    const float* n2w   = (const float*)d_in[9];
    const float* n2b   = (const float*)d_in[10];
    const float* fc1w  = (const float*)d_in[11];
    const float* fc1b  = (const float*)d_in[12];
    const float* fc2w  = (const float*)d_in[13];
    const float* fc2b  = (const float*)d_in[14];
    float* out = (float*)d_out;

    float *xln, *qkvs, *xf, *qkvf, *attn, *outf, *x2, *hln, *h1;
    cudaGetSymbolAddress((void**)&xln,  g_xln);
    cudaGetSymbolAddress((void**)&qkvs, g_qkvs);
    cudaGetSymbolAddress((void**)&xf,   g_xf);
    cudaGetSymbolAddress((void**)&qkvf, g_qkvf);
    cudaGetSymbolAddress((void**)&attn, g_attn);
    cudaGetSymbolAddress((void**)&outf, g_outf);
    cudaGetSymbolAddress((void**)&x2,   g_x2);
    cudaGetSymbolAddress((void**)&hln,  g_hln);
    cudaGetSymbolAddress((void**)&h1,   g_h1);

    cudaFuncSetAttribute(gemm_mma<0>, cudaFuncAttributeMaxDynamicSharedMemorySize, GEMM_SMEM);
    cudaFuncSetAttribute(gemm_mma<1>, cudaFuncAttributeMaxDynamicSharedMemorySize, GEMM_SMEM);
    cudaFuncSetAttribute(gemm_mma<2>, cudaFuncAttributeMaxDynamicSharedMemorySize, GEMM_SMEM);
    cudaFuncSetAttribute(gemm_mma<3>, cudaFuncAttributeMaxDynamicSharedMemorySize, GEMM_SMEM);

    init_dft_kernel<<<17, 256>>>();

    // LN1 (+ window partition)
    ln_kernel<<<TOKS, 256>>>(x, n1w, n1b, xln, 1);

    // spatial qkv: (131072 x 768)
    gemm_mma<0><<<dim3(768 / 128, TOKS / 128), 256, GEMM_SMEM>>>(
        xln, qkvw, qkvb, qkvs, TOKS, 768, 256, nullptr);

    // spectral input
    fft_fwd_kernel<<<NWIN, 256>>>(xln, xf);

    // spectral qkv: (135168 x 768)
    gemm_mma<0><<<dim3(768 / 128, TOKF / 128), 256, GEMM_SMEM>>>(
        xf, qkvw, qkvb, qkvf, TOKF, 768, 256, nullptr);

    // attention
    attn_kernel<NTOK, true ><<<dim3(NWIN, HEADS), NTOK>>>(qkvs, rpb, attn);
    attn_kernel<NF,   false><<<dim3(NWIN, HEADS), NF  >>>(qkvf, nullptr, outf);

    // irfft of spectral branch -> accumulate into spatial attn output
    fft_inv_kernel<<<NWIN, 256>>>(outf, attn);

    // proj + window reverse + shortcut -> x2
    gemm_mma<3><<<dim3(256 / 128, TOKS / 128), 256, GEMM_SMEM>>>(
        attn, projw, projb, x2, TOKS, 256, 256, x);

    // LN2
    ln_kernel<<<TOKS, 256>>>(x2, n2w, n2b, hln, 0);

    // fc1 + GELU
    gemm_mma<1><<<dim3(1024 / 128, TOKS / 128), 256, GEMM_SMEM>>>(
        hln, fc1w, fc1b, h1, TOKS, 1024, 256, nullptr);

    // fc2 + residual -> out
    gemm_mma<2><<<dim3(256 / 128, TOKS / 128), 256, GEMM_SMEM>>>(
        h1, fc2w, fc2b, out, TOKS, 256, 1024, x2);
}

// round 5
// speedup vs baseline: 1.9941x; 1.0969x over previous
#include <cuda_runtime.h>
#include <math.h>
#include <stdint.h>

// ---------------------------------------------------------------------------
// Problem constants
// ---------------------------------------------------------------------------
#define CC      256
#define WS      8
#define NTOK    64
#define NF      66
#define HEADS   8
#define HD      32
#define NWIN    2048
#define TOKS    131072
#define SCALE   0.17677669529663687f

// ---------------------------------------------------------------------------
// Scratch
// ---------------------------------------------------------------------------
__device__ float g_xln [ (size_t)NWIN * NTOK * CC ];
__device__ float g_qkvs[ (size_t)NWIN * NTOK * 3 * CC ];
__device__ float g_qkvf[ (size_t)NWIN * NF   * 3 * CC ];
__device__ float g_attn[ (size_t)NWIN * NTOK * CC ];
__device__ float g_outf[ (size_t)NWIN * NF   * CC ];
__device__ float g_x2  [ (size_t)TOKS * CC ];
__device__ float g_hln [ (size_t)TOKS * CC ];
__device__ float g_h1  [ (size_t)TOKS * 4 * CC ];
__device__ float g_dftF[ NF * NTOK ];
__device__ float g_dftI[ NTOK * NF ];

// ---------------------------------------------------------------------------
// Helpers
// ---------------------------------------------------------------------------
__device__ __forceinline__ uint32_t smem_u32(const void* p) {
    uint32_t a;
    asm("{ .reg .u64 t; cvta.to.shared.u64 t, %1; cvt.u32.u64 %0, t; }"
        : "=r"(a) : "l"(p));
    return a;
}

#define CP_ASYNC16(dst_u32, src_ptr) \
    asm volatile("cp.async.cg.shared.global [%0], [%1], 16;" \
        :: "r"(dst_u32), "l"(src_ptr))
#define CP_COMMIT() asm volatile("cp.async.commit_group;")
#define CP_WAIT1()  asm volatile("cp.async.wait_group 1;")
#define CP_WAIT0()  asm volatile("cp.async.wait_group 0;")

__device__ __forceinline__ void mma16n8k8(float* c, const uint32_t* a,
                                          const uint32_t* b) {
    asm volatile(
        "mma.sync.aligned.m16n8k8.row.col.f32.tf32.tf32.f32 "
        "{%0,%1,%2,%3}, {%4,%5,%6,%7}, {%8,%9}, {%0,%1,%2,%3};"
        : "+f"(c[0]), "+f"(c[1]), "+f"(c[2]), "+f"(c[3])
        : "r"(a[0]), "r"(a[1]), "r"(a[2]), "r"(a[3]), "r"(b[0]), "r"(b[1]));
}

__device__ __forceinline__ int win2pix(int t) {
    int b   = t >> 16;
    int rem = t & 65535;
    int wl  = rem >> 6;
    int n   = rem & 63;
    int wh  = wl >> 5, ww = wl & 31;
    int i   = n >> 3,  j  = n & 7;
    return (b * 256 + wh * 8 + i) * 256 + (ww * 8 + j);
}

// ---------------------------------------------------------------------------
// DFT matrix init
// ---------------------------------------------------------------------------
__global__ void init_dft_kernel() {
    int i = blockIdx.x * blockDim.x + threadIdx.x;
    if (i < NF * NTOK) {
        int f = i / NTOK, n = i % NTOK;
        float v;
        if (f < 33) v =  cospif((float)(f * n) / 32.0f);
        else        v = -sinpif((float)((f - 33) * n) / 32.0f);
        g_dftF[i] = v * 0.125f;
    }
    if (i < NTOK * NF) {
        int n = i / NF, r = i % NF;
        float v;
        if (r == 0)        v = 1.0f;
        else if (r < 32)   v =  2.0f * cospif((float)(r * n) / 32.0f);
        else if (r == 32)  v =  cospif((float)n);
        else if (r == 33 || r == 65) v = 0.0f;
        else               v = -2.0f * sinpif((float)((r - 33) * n) / 32.0f);
        g_dftI[i] = v * 0.125f;
    }
}

// ---------------------------------------------------------------------------
// LayerNorm
// ---------------------------------------------------------------------------
__global__ void ln_kernel(const float* __restrict__ xin,
                          const float* __restrict__ w,
                          const float* __restrict__ b,
                          float* __restrict__ out, int winmap) {
    __shared__ float red[16];
    int t = blockIdx.x, c = threadIdx.x;
    int rin = winmap ? win2pix(t) : t;
    float v = xin[(size_t)rin * CC + c];
    float s = v, sq = v * v;
    #pragma unroll
    for (int o = 16; o; o >>= 1) {
        s  += __shfl_down_sync(0xffffffffu, s,  o);
        sq += __shfl_down_sync(0xffffffffu, sq, o);
    }
    int warp = c >> 5, lane = c & 31;
    if (lane == 0) { red[warp] = s; red[8 + warp] = sq; }
    __syncthreads();
    if (c == 0) {
        float S = 0.f, Q = 0.f;
        #pragma unroll
        for (int i = 0; i < 8; i++) { S += red[i]; Q += red[8 + i]; }
        red[0] = S * (1.0f / CC);
        red[8] = Q * (1.0f / CC);
    }
    __syncthreads();
    float mean = red[0];
    float var  = red[8] - mean * mean;
    out[(size_t)t * CC + c] = (v - mean) * rsqrtf(var + 1e-5f) * w[c] + b[c];
}

// ---------------------------------------------------------------------------
// tf32 mma.sync GEMM: C[M,N] = A[M,K] @ W[N,K]^T + bias (+ epilogue)
// 128x256 CTA tile, BK=32, 8 warps (2x4), warp tile 64x64.
// cp.async 2-stage pipeline, smem stride 36 floats.
// EPI: 0 plain, 1 GELU, 2 +res[m*N+n], 3 window-reverse +res
// ---------------------------------------------------------------------------
#define SMS 36
#define A_STAGE (128 * SMS)
#define B_STAGE (256 * SMS)
#define STG_TOT (A_STAGE + B_STAGE)
#define GEMM_SMEM (2 * STG_TOT * 4)

template<int EPI>
__global__ __launch_bounds__(256, 1)
void gemm_mma(const float* __restrict__ A, const float* __restrict__ W,
              const float* __restrict__ bias, float* __restrict__ C,
              int M, int N, int K, const float* __restrict__ res) {
    extern __shared__ float sm[];
    float* AsBase = sm;                      // [2][128][SMS]
    float* BsBase = sm + 2 * A_STAGE;        // [2][256][SMS]
    uint32_t sA = smem_u32(AsBase);
    uint32_t sB = smem_u32(BsBase);

    int tid = threadIdx.x;
    int m0 = blockIdx.y * 128, n0 = blockIdx.x * 256;
    int wid = tid >> 5, lane = tid & 31;
    int wm = (wid & 1) * 64, wn = (wid >> 1) * 64;
    int grp = lane >> 2, tg = lane & 3;

    float acc[4][8][4];
    #pragma unroll
    for (int a = 0; a < 4; a++)
        #pragma unroll
        for (int b = 0; b < 8; b++)
            #pragma unroll
            for (int c = 0; c < 4; c++) acc[a][b][c] = 0.f;

    const int NC = K / 32;

    // prologue: chunk 0 -> stage 0
    #pragma unroll
    for (int t = 0; t < 4; t++) {
        int idx = tid + t * 256;
        int row = idx >> 3, q = idx & 7;
        CP_ASYNC16(sA + (uint32_t)(row * SMS + q * 4) * 4u,
                   A + (size_t)(m0 + row) * K + q * 4);
    }
    #pragma unroll
    for (int t = 0; t < 8; t++) {
        int idx = tid + t * 256;
        int row = idx >> 3, q = idx & 7;
        CP_ASYNC16(sB + (uint32_t)(row * SMS + q * 4) * 4u,
                   W + (size_t)(n0 + row) * K + q * 4);
    }
    CP_COMMIT();

    for (int i = 0; i < NC; i++) {
        int s = i & 1;
        if (i + 1 < NC) {
            int s2 = s ^ 1;
            #pragma unroll
            for (int t = 0; t < 4; t++) {
                int idx = tid + t * 256;
                int row = idx >> 3, q = idx & 7;
                CP_ASYNC16(sA + (uint32_t)(s2 * A_STAGE + row * SMS + q * 4) * 4u,
                           A + (size_t)(m0 + row) * K + (i + 1) * 32 + q * 4);
            }
            #pragma unroll
            for (int t = 0; t < 8; t++) {
                int idx = tid + t * 256;
                int row = idx >> 3, q = idx & 7;
                CP_ASYNC16(sB + (uint32_t)(s2 * B_STAGE + row * SMS + q * 4) * 4u,
                           W + (size_t)(n0 + row) * K + (i + 1) * 32 + q * 4);
            }
            CP_COMMIT();
            CP_WAIT1();
        } else {
            CP_WAIT0();
        }
        __syncthreads();

        const float* As = AsBase + s * A_STAGE;
        const float* Bs = BsBase + s * B_STAGE;
        #pragma unroll
        for (int ks = 0; ks < 4; ks++) {
            uint32_t af[4][4];
            uint32_t bf[8][2];
            #pragma unroll
            for (int mi = 0; mi < 4; mi++) {
                int r = wm + mi * 16 + grp;
                af[mi][0] = __float_as_uint(As[r * SMS + ks * 8 + tg]);
                af[mi][1] = __float_as_uint(As[(r + 8) * SMS + ks * 8 + tg]);
                af[mi][2] = __float_as_uint(As[r * SMS + ks * 8 + tg + 4]);
                af[mi][3] = __float_as_uint(As[(r + 8) * SMS + ks * 8 + tg + 4]);
            }
            #pragma unroll
            for (int ni = 0; ni < 8; ni++) {
                int r = wn + ni * 8 + grp;
                bf[ni][0] = __float_as_uint(Bs[r * SMS + ks * 8 + tg]);
                bf[ni][1] = __float_as_uint(Bs[r * SMS + ks * 8 + tg + 4]);
            }
            #pragma unroll
            for (int mi = 0; mi < 4; mi++)
                #pragma unroll
                for (int ni = 0; ni < 8; ni++)
                    mma16n8k8(acc[mi][ni], af[mi], bf[ni]);
        }
        __syncthreads();
    }

    // epilogue
    #pragma unroll
    for (int mi = 0; mi < 4; mi++) {
        #pragma unroll
        for (int half = 0; half < 2; half++) {
            int m = m0 + wm + mi * 16 + grp + half * 8;
            size_t orow = (EPI == 3) ? (size_t)win2pix(m) * N : (size_t)m * N;
            #pragma unroll
            for (int ni = 0; ni < 8; ni++) {
                int n = n0 + wn + ni * 8 + tg * 2;
                float vx = acc[mi][ni][half * 2 + 0] + bias[n];
                float vy = acc[mi][ni][half * 2 + 1] + bias[n + 1];
                if (EPI == 1) {
                    vx = 0.5f * vx * (1.0f + erff(vx * 0.7071067811865476f));
                    vy = 0.5f * vy * (1.0f + erff(vy * 0.7071067811865476f));
                } else if (EPI == 2) {
                    vx += res[(size_t)m * N + n];
                    vy += res[(size_t)m * N + n + 1];
                } else if (EPI == 3) {
                    vx += res[orow + n];
                    vy += res[orow + n + 1];
                }
                *(float2*)(C + orow + n) = make_float2(vx, vy);
            }
        }
    }
}

// ---------------------------------------------------------------------------
// Fused spectral qkv: qkvf[w,f,ch] = sum_n F[f,n]*qkvs[w,n,ch] + bias corr.
// (DFT commutes with the linear qkv projection; row f=0 needs -7*b since
//  sum_n F[0,n] = 8, all other rows sum to 0.)
// grid (NWIN, 3), 256 threads; thread owns one of 768 channels, holds the
// 64-token column in registers, 1 broadcast-LDS per FMA.
// ---------------------------------------------------------------------------
__global__ __launch_bounds__(256)
void spec_qkv_kernel(const float* __restrict__ qkvs,
                     const float* __restrict__ qkvb,
                     float* __restrict__ qkvf) {
    __shared__ float F[NF * NTOK];
    int w = blockIdx.x;
    int tid = threadIdx.x;
    int ch = blockIdx.y * 256 + tid;
    for (int m = tid; m < NF * NTOK; m += 256) F[m] = g_dftF[m];

    float xr[NTOK];
    const float* src = qkvs + (size_t)w * NTOK * 768 + ch;
    #pragma unroll 16
    for (int n = 0; n < NTOK; n++) xr[n] = src[(size_t)n * 768];
    __syncthreads();

    float bb = qkvb[ch];
    float* dst = qkvf + (size_t)w * NF * 768 + ch;
    for (int f = 0; f < NF; f++) {
        const float* Fr = F + f * NTOK;
        float s = 0.f;
        #pragma unroll
        for (int n = 0; n < NTOK; n++) s += Fr[n] * xr[n];
        s += (f == 0) ? -7.0f * bb : bb;
        dst[(size_t)f * 768] = s;
    }
}

// ---------------------------------------------------------------------------
// Inverse rfft accumulate: acc[w,n,c] += sum_r Wi[n,r]*outf[w,r,c]
// Thread owns channel c, holds 66 spectral values in registers.
// ---------------------------------------------------------------------------
__global__ __launch_bounds__(256)
void ifft_acc_kernel(const float* __restrict__ outf,
                     float* __restrict__ acc) {
    __shared__ float Wi[NTOK * NF];
    int w = blockIdx.x;
    int c = threadIdx.x;
    for (int m = c; m < NTOK * NF; m += 256) Wi[m] = g_dftI[m];

    float fr[NF];
    const float* src = outf + (size_t)w * NF * CC + c;
    #pragma unroll 11
    for (int r = 0; r < NF; r++) fr[r] = src[(size_t)r * CC];
    __syncthreads();

    float* dst = acc + (size_t)w * NTOK * CC + c;
    for (int n = 0; n < NTOK; n++) {
        const float* Wr = Wi + n * NF;
        float s = 0.f;
        #pragma unroll
        for (int r = 0; r < NF; r++) s += Wr[r] * fr[r];
        dst[(size_t)n * CC] += s;
    }
}

// ---------------------------------------------------------------------------
// Window attention
// ---------------------------------------------------------------------------
template<int NT, bool BIAS>
__global__ void attn_kernel(const float* __restrict__ qkv,
                            const float* __restrict__ rpb,
                            float* __restrict__ outp) {
    __shared__ float qs[NT][33];
    __shared__ float ks[NT][33];
    __shared__ float vs[NT][33];
    __shared__ float ss[NT][NT + 1];
    __shared__ float rpb_s[BIAS ? 225 : 1];

    int w = blockIdx.x, h = blockIdx.y;
    int row = threadIdx.x;

    {
        size_t base = ((size_t)w * NT + row) * 768 + h * 32;
        #pragma unroll
        for (int d = 0; d < HD; d++) {
            qs[row][d] = qkv[base + d];
            ks[row][d] = qkv[base + 256 + d];
            vs[row][d] = qkv[base + 512 + d];
        }
    }
    if (BIAS) {
        for (int m = row; m < 225; m += NT) rpb_s[m] = rpb[m * HEADS + h];
    }
    __syncthreads();

    float qr[HD];
    #pragma unroll
    for (int d = 0; d < HD; d++) qr[d] = qs[row][d];

    float mx = -1e30f;
    int yi = row >> 3, xi = row & 7;
    for (int j = 0; j < NT; j++) {
        float s = 0.f;
        #pragma unroll
        for (int d = 0; d < HD; d++) s += qr[d] * ks[j][d];
        s *= SCALE;
        if (BIAS) {
            int yj = j >> 3, xj = j & 7;
            int idx = (yi - yj + 7) * 15 + (xi - xj + 7);
            s += rpb_s[idx];
        }
        ss[row][j] = s;
        mx = fmaxf(mx, s);
    }
    float sum = 0.f;
    for (int j = 0; j < NT; j++) {
        float e = expf(ss[row][j] - mx);
        ss[row][j] = e;
        sum += e;
    }
    float inv = 1.0f / sum;

    float acc[HD];
    #pragma unroll
    for (int d = 0; d < HD; d++) acc[d] = 0.f;
    for (int j = 0; j < NT; j++) {
        float p = ss[row][j];
        #pragma unroll
        for (int d = 0; d < HD; d++) acc[d] += p * vs[j][d];
    }
    size_t obase = ((size_t)w * NT + row) * CC + h * 32;
    #pragma unroll
    for (int d = 0; d < HD; d++) outp[obase + d] = acc[d] * inv;
}

// ---------------------------------------------------------------------------
// Launch
// ---------------------------------------------------------------------------
extern "C" void kernel_launch(void* const* d_in, const int* in_sizes, int n_in,
                              void* d_out, int out_size) {
    (void)in_sizes; (void)n_in; (void)out_size;
    const float* x     = (const float*)d_in[0];
    const float* n1w   = (const float*)d_in[2];
    const float* n1b   = (const float*)d_in[3];
    const float* qkvw  = (const float*)d_in[4];
    const float* qkvb  = (const float*)d_in[5];
    const float* rpb   = (const float*)d_in[6];
    const float* projw = (const float*)d_in[7];
    const float* projb = (const float*)d_in[8];
    const float* n2w   = (const float*)d_in[9];
    const float* n2b   = (const float*)d_in[10];
    const float* fc1w  = (const float*)d_in[11];
    const float* fc1b  = (const float*)d_in[12];
    const float* fc2w  = (const float*)d_in[13];
    const float* fc2b  = (const float*)d_in[14];
    float* out = (float*)d_out;

    float *xln, *qkvs, *qkvf, *attn, *outf, *x2, *hln, *h1;
    cudaGetSymbolAddress((void**)&xln,  g_xln);
    cudaGetSymbolAddress((void**)&qkvs, g_qkvs);
    cudaGetSymbolAddress((void**)&qkvf, g_qkvf);
    cudaGetSymbolAddress((void**)&attn, g_attn);
    cudaGetSymbolAddress((void**)&outf, g_outf);
    cudaGetSymbolAddress((void**)&x2,   g_x2);
    cudaGetSymbolAddress((void**)&hln,  g_hln);
    cudaGetSymbolAddress((void**)&h1,   g_h1);

    cudaFuncSetAttribute(gemm_mma<0>, cudaFuncAttributeMaxDynamicSharedMemorySize, GEMM_SMEM);
    cudaFuncSetAttribute(gemm_mma<1>, cudaFuncAttributeMaxDynamicSharedMemorySize, GEMM_SMEM);
    cudaFuncSetAttribute(gemm_mma<2>, cudaFuncAttributeMaxDynamicSharedMemorySize, GEMM_SMEM);
    cudaFuncSetAttribute(gemm_mma<3>, cudaFuncAttributeMaxDynamicSharedMemorySize, GEMM_SMEM);

    init_dft_kernel<<<17, 256>>>();

    // LN1 (+ window partition)
    ln_kernel<<<TOKS, 256>>>(x, n1w, n1b, xln, 1);

    // spatial qkv: (131072 x 768)
    gemm_mma<0><<<dim3(768 / 256, TOKS / 128), 256, GEMM_SMEM>>>(
        xln, qkvw, qkvb, qkvs, TOKS, 768, 256, nullptr);

    // spectral qkv via DFT of spatial qkv (linearity)
    spec_qkv_kernel<<<dim3(NWIN, 3), 256>>>(qkvs, qkvb, qkvf);

    // attention
    attn_kernel<NTOK, true ><<<dim3(NWIN, HEADS), NTOK>>>(qkvs, rpb, attn);
    attn_kernel<NF,   false><<<dim3(NWIN, HEADS), NF  >>>(qkvf, nullptr, outf);

    // irfft of spectral branch -> accumulate into spatial attn output
    ifft_acc_kernel<<<NWIN, 256>>>(outf, attn);

    // proj + window reverse + shortcut -> x2
    gemm_mma<3><<<dim3(256 / 256, TOKS / 128), 256, GEMM_SMEM>>>(
        attn, projw, projb, x2, TOKS, 256, 256, x);

    // LN2
    ln_kernel<<<TOKS, 256>>>(x2, n2w, n2b, hln, 0);

    // fc1 + GELU
    gemm_mma<1><<<dim3(1024 / 256, TOKS / 128), 256, GEMM_SMEM>>>(
        hln, fc1w, fc1b, h1, TOKS, 1024, 256, nullptr);

    // fc2 + residual -> out
    gemm_mma<2><<<dim3(256 / 256, TOKS / 128), 256, GEMM_SMEM>>>(
        h1, fc2w, fc2b, out, TOKS, 256, 1024, x2);
}

// round 6
// speedup vs baseline: 2.9068x; 1.4577x over previous
#include <cuda_runtime.h>
#include <math.h>
#include <stdint.h>

// ---------------------------------------------------------------------------
// Problem constants
// ---------------------------------------------------------------------------
#define CC      256
#define WS      8
#define NTOK    64
#define NF      66
#define HEADS   8
#define HD      32
#define NWIN    2048
#define TOKS    131072
#define SCALE   0.17677669529663687f

// ---------------------------------------------------------------------------
// Scratch
// ---------------------------------------------------------------------------
__device__ float g_xln [ (size_t)NWIN * NTOK * CC ];
__device__ float g_qkvs[ (size_t)NWIN * NTOK * 3 * CC ];
__device__ float g_qkvf[ (size_t)NWIN * NF   * 3 * CC ];
__device__ float g_attn[ (size_t)NWIN * NTOK * CC ];
__device__ float g_outf[ (size_t)NWIN * NF   * CC ];
__device__ float g_x2  [ (size_t)TOKS * CC ];
__device__ float g_hln [ (size_t)TOKS * CC ];
__device__ float g_h1  [ (size_t)TOKS * 4 * CC ];
__device__ float g_dftF[ NF * NTOK ];
__device__ float g_dftI[ NTOK * NF ];

// ---------------------------------------------------------------------------
// Helpers
// ---------------------------------------------------------------------------
__device__ __forceinline__ uint32_t smem_u32(const void* p) {
    uint32_t a;
    asm("{ .reg .u64 t; cvta.to.shared.u64 t, %1; cvt.u32.u64 %0, t; }"
        : "=r"(a) : "l"(p));
    return a;
}

#define CP_ASYNC16(dst_u32, src_ptr) \
    asm volatile("cp.async.cg.shared.global [%0], [%1], 16;" \
        :: "r"(dst_u32), "l"(src_ptr))
#define CP_COMMIT() asm volatile("cp.async.commit_group;")
#define CP_WAIT1()  asm volatile("cp.async.wait_group 1;")
#define CP_WAIT0()  asm volatile("cp.async.wait_group 0;")

__device__ __forceinline__ void mma16n8k8(float* c, const uint32_t* a,
                                          const uint32_t* b) {
    asm volatile(
        "mma.sync.aligned.m16n8k8.row.col.f32.tf32.tf32.f32 "
        "{%0,%1,%2,%3}, {%4,%5,%6,%7}, {%8,%9}, {%0,%1,%2,%3};"
        : "+f"(c[0]), "+f"(c[1]), "+f"(c[2]), "+f"(c[3])
        : "r"(a[0]), "r"(a[1]), "r"(a[2]), "r"(a[3]), "r"(b[0]), "r"(b[1]));
}

__device__ __forceinline__ int win2pix(int t) {
    int b   = t >> 16;
    int rem = t & 65535;
    int wl  = rem >> 6;
    int n   = rem & 63;
    int wh  = wl >> 5, ww = wl & 31;
    int i   = n >> 3,  j  = n & 7;
    return (b * 256 + wh * 8 + i) * 256 + (ww * 8 + j);
}

__device__ __forceinline__ float dot4(float4 a, float4 b) {
    return a.x * b.x + a.y * b.y + a.z * b.z + a.w * b.w;
}

// ---------------------------------------------------------------------------
// DFT matrix init
// ---------------------------------------------------------------------------
__global__ void init_dft_kernel() {
    int i = blockIdx.x * blockDim.x + threadIdx.x;
    if (i < NF * NTOK) {
        int f = i / NTOK, n = i % NTOK;
        float v;
        if (f < 33) v =  cospif((float)(f * n) / 32.0f);
        else        v = -sinpif((float)((f - 33) * n) / 32.0f);
        g_dftF[i] = v * 0.125f;
    }
    if (i < NTOK * NF) {
        int n = i / NF, r = i % NF;
        float v;
        if (r == 0)        v = 1.0f;
        else if (r < 32)   v =  2.0f * cospif((float)(r * n) / 32.0f);
        else if (r == 32)  v =  cospif((float)n);
        else if (r == 33 || r == 65) v = 0.0f;
        else               v = -2.0f * sinpif((float)((r - 33) * n) / 32.0f);
        g_dftI[i] = v * 0.125f;
    }
}

// ---------------------------------------------------------------------------
// LayerNorm
// ---------------------------------------------------------------------------
__global__ void ln_kernel(const float* __restrict__ xin,
                          const float* __restrict__ w,
                          const float* __restrict__ b,
                          float* __restrict__ out, int winmap) {
    __shared__ float red[16];
    int t = blockIdx.x, c = threadIdx.x;
    int rin = winmap ? win2pix(t) : t;
    float v = xin[(size_t)rin * CC + c];
    float s = v, sq = v * v;
    #pragma unroll
    for (int o = 16; o; o >>= 1) {
        s  += __shfl_down_sync(0xffffffffu, s,  o);
        sq += __shfl_down_sync(0xffffffffu, sq, o);
    }
    int warp = c >> 5, lane = c & 31;
    if (lane == 0) { red[warp] = s; red[8 + warp] = sq; }
    __syncthreads();
    if (c == 0) {
        float S = 0.f, Q = 0.f;
        #pragma unroll
        for (int i = 0; i < 8; i++) { S += red[i]; Q += red[8 + i]; }
        red[0] = S * (1.0f / CC);
        red[8] = Q * (1.0f / CC);
    }
    __syncthreads();
    float mean = red[0];
    float var  = red[8] - mean * mean;
    out[(size_t)t * CC + c] = (v - mean) * rsqrtf(var + 1e-5f) * w[c] + b[c];
}

// ---------------------------------------------------------------------------
// tf32 mma.sync GEMM (unchanged from R4): C = A @ W^T + bias (+ epilogue)
// ---------------------------------------------------------------------------
#define SMS 36
#define A_STAGE (128 * SMS)
#define B_STAGE (256 * SMS)
#define STG_TOT (A_STAGE + B_STAGE)
#define GEMM_SMEM (2 * STG_TOT * 4)

template<int EPI>
__global__ __launch_bounds__(256, 1)
void gemm_mma(const float* __restrict__ A, const float* __restrict__ W,
              const float* __restrict__ bias, float* __restrict__ C,
              int M, int N, int K, const float* __restrict__ res) {
    extern __shared__ float sm[];
    float* AsBase = sm;
    float* BsBase = sm + 2 * A_STAGE;
    uint32_t sA = smem_u32(AsBase);
    uint32_t sB = smem_u32(BsBase);

    int tid = threadIdx.x;
    int m0 = blockIdx.y * 128, n0 = blockIdx.x * 256;
    int wid = tid >> 5, lane = tid & 31;
    int wm = (wid & 1) * 64, wn = (wid >> 1) * 64;
    int grp = lane >> 2, tg = lane & 3;

    float acc[4][8][4];
    #pragma unroll
    for (int a = 0; a < 4; a++)
        #pragma unroll
        for (int b = 0; b < 8; b++)
            #pragma unroll
            for (int c = 0; c < 4; c++) acc[a][b][c] = 0.f;

    const int NC = K / 32;

    #pragma unroll
    for (int t = 0; t < 4; t++) {
        int idx = tid + t * 256;
        int row = idx >> 3, q = idx & 7;
        CP_ASYNC16(sA + (uint32_t)(row * SMS + q * 4) * 4u,
                   A + (size_t)(m0 + row) * K + q * 4);
    }
    #pragma unroll
    for (int t = 0; t < 8; t++) {
        int idx = tid + t * 256;
        int row = idx >> 3, q = idx & 7;
        CP_ASYNC16(sB + (uint32_t)(row * SMS + q * 4) * 4u,
                   W + (size_t)(n0 + row) * K + q * 4);
    }
    CP_COMMIT();

    for (int i = 0; i < NC; i++) {
        int s = i & 1;
        if (i + 1 < NC) {
            int s2 = s ^ 1;
            #pragma unroll
            for (int t = 0; t < 4; t++) {
                int idx = tid + t * 256;
                int row = idx >> 3, q = idx & 7;
                CP_ASYNC16(sA + (uint32_t)(s2 * A_STAGE + row * SMS + q * 4) * 4u,
                           A + (size_t)(m0 + row) * K + (i + 1) * 32 + q * 4);
            }
            #pragma unroll
            for (int t = 0; t < 8; t++) {
                int idx = tid + t * 256;
                int row = idx >> 3, q = idx & 7;
                CP_ASYNC16(sB + (uint32_t)(s2 * B_STAGE + row * SMS + q * 4) * 4u,
                           W + (size_t)(n0 + row) * K + (i + 1) * 32 + q * 4);
            }
            CP_COMMIT();
            CP_WAIT1();
        } else {
            CP_WAIT0();
        }
        __syncthreads();

        const float* As = AsBase + s * A_STAGE;
        const float* Bs = BsBase + s * B_STAGE;
        #pragma unroll
        for (int ks = 0; ks < 4; ks++) {
            uint32_t af[4][4];
            uint32_t bf[8][2];
            #pragma unroll
            for (int mi = 0; mi < 4; mi++) {
                int r = wm + mi * 16 + grp;
                af[mi][0] = __float_as_uint(As[r * SMS + ks * 8 + tg]);
                af[mi][1] = __float_as_uint(As[(r + 8) * SMS + ks * 8 + tg]);
                af[mi][2] = __float_as_uint(As[r * SMS + ks * 8 + tg + 4]);
                af[mi][3] = __float_as_uint(As[(r + 8) * SMS + ks * 8 + tg + 4]);
            }
            #pragma unroll
            for (int ni = 0; ni < 8; ni++) {
                int r = wn + ni * 8 + grp;
                bf[ni][0] = __float_as_uint(Bs[r * SMS + ks * 8 + tg]);
                bf[ni][1] = __float_as_uint(Bs[r * SMS + ks * 8 + tg + 4]);
            }
            #pragma unroll
            for (int mi = 0; mi < 4; mi++)
                #pragma unroll
                for (int ni = 0; ni < 8; ni++)
                    mma16n8k8(acc[mi][ni], af[mi], bf[ni]);
        }
        __syncthreads();
    }

    #pragma unroll
    for (int mi = 0; mi < 4; mi++) {
        #pragma unroll
        for (int half = 0; half < 2; half++) {
            int m = m0 + wm + mi * 16 + grp + half * 8;
            size_t orow = (EPI == 3) ? (size_t)win2pix(m) * N : (size_t)m * N;
            #pragma unroll
            for (int ni = 0; ni < 8; ni++) {
                int n = n0 + wn + ni * 8 + tg * 2;
                float vx = acc[mi][ni][half * 2 + 0] + bias[n];
                float vy = acc[mi][ni][half * 2 + 1] + bias[n + 1];
                if (EPI == 1) {
                    vx = 0.5f * vx * (1.0f + erff(vx * 0.7071067811865476f));
                    vy = 0.5f * vy * (1.0f + erff(vy * 0.7071067811865476f));
                } else if (EPI == 2) {
                    vx += res[(size_t)m * N + n];
                    vy += res[(size_t)m * N + n + 1];
                } else if (EPI == 3) {
                    vx += res[orow + n];
                    vy += res[orow + n + 1];
                }
                *(float2*)(C + orow + n) = make_float2(vx, vy);
            }
        }
    }
}

// ---------------------------------------------------------------------------
// Fused spectral qkv (ILP version): 2 DFT rows per iter, float4 F reads.
// ---------------------------------------------------------------------------
__global__ __launch_bounds__(256)
void spec_qkv_kernel(const float* __restrict__ qkvs,
                     const float* __restrict__ qkvb,
                     float* __restrict__ qkvf) {
    __shared__ float F[NF * NTOK];
    int w = blockIdx.x;
    int tid = threadIdx.x;
    int ch = blockIdx.y * 256 + tid;
    for (int m = tid; m < NF * NTOK; m += 256) F[m] = g_dftF[m];

    float xr[NTOK];
    const float* src = qkvs + (size_t)w * NTOK * 768 + ch;
    #pragma unroll 16
    for (int n = 0; n < NTOK; n++) xr[n] = src[(size_t)n * 768];
    __syncthreads();

    float bb = qkvb[ch];
    float* dst = qkvf + (size_t)w * NF * 768 + ch;
    #pragma unroll 1
    for (int f = 0; f < NF; f += 2) {
        const float4* F0 = (const float4*)(F + f * NTOK);
        const float4* F1 = (const float4*)(F + (f + 1) * NTOK);
        float s0a = 0.f, s0b = 0.f, s1a = 0.f, s1b = 0.f;
        #pragma unroll
        for (int q = 0; q < 16; q++) {
            float4 xv = make_float4(xr[q*4], xr[q*4+1], xr[q*4+2], xr[q*4+3]);
            float4 a0 = F0[q];
            float4 a1 = F1[q];
            s0a += a0.x * xv.x + a0.y * xv.y;
            s0b += a0.z * xv.z + a0.w * xv.w;
            s1a += a1.x * xv.x + a1.y * xv.y;
            s1b += a1.z * xv.z + a1.w * xv.w;
        }
        float s0 = s0a + s0b + ((f == 0) ? -7.0f * bb : bb);
        float s1 = s1a + s1b + bb;
        dst[(size_t)f * 768]       = s0;
        dst[(size_t)(f + 1) * 768] = s1;
    }
}

// ---------------------------------------------------------------------------
// Inverse rfft accumulate (ILP version): 2 output tokens per iter,
// float4 reads from padded Wi rows (stride 68).
// ---------------------------------------------------------------------------
__global__ __launch_bounds__(256)
void ifft_acc_kernel(const float* __restrict__ outf,
                     float* __restrict__ acc) {
    __shared__ float Wi[NTOK * 68];
    int w = blockIdx.x;
    int c = threadIdx.x;
    for (int m = c; m < NTOK * NF; m += 256) {
        int n = m / NF, r = m % NF;
        Wi[n * 68 + r] = g_dftI[m];
    }

    float fr[NF];
    const float* src = outf + (size_t)w * NF * CC + c;
    #pragma unroll 11
    for (int r = 0; r < NF; r++) fr[r] = src[(size_t)r * CC];
    __syncthreads();

    float* dst = acc + (size_t)w * NTOK * CC + c;
    #pragma unroll 1
    for (int n = 0; n < NTOK; n += 2) {
        const float4* W0 = (const float4*)(Wi + n * 68);
        const float4* W1 = (const float4*)(Wi + (n + 1) * 68);
        float s0a = 0.f, s0b = 0.f, s1a = 0.f, s1b = 0.f;
        #pragma unroll
        for (int q = 0; q < 16; q++) {
            float4 xv = make_float4(fr[q*4], fr[q*4+1], fr[q*4+2], fr[q*4+3]);
            float4 a0 = W0[q];
            float4 a1 = W1[q];
            s0a += a0.x * xv.x + a0.y * xv.y;
            s0b += a0.z * xv.z + a0.w * xv.w;
            s1a += a1.x * xv.x + a1.y * xv.y;
            s1b += a1.z * xv.z + a1.w * xv.w;
        }
        const float* W0s = Wi + n * 68;
        const float* W1s = Wi + (n + 1) * 68;
        float s0 = s0a + s0b + W0s[64] * fr[64] + W0s[65] * fr[65];
        float s1 = s1a + s1b + W1s[64] * fr[64] + W1s[65] * fr[65];
        dst[(size_t)n * CC]       += s0;
        dst[(size_t)(n + 1) * CC] += s1;
    }
}

// ---------------------------------------------------------------------------
// Window attention (ILP version): float4 K/V reads, 4-wide j blocking with
// independent accumulators, SCALE folded into q, odd ss stride.
// ---------------------------------------------------------------------------
template<int NT, bool BIAS>
__global__ void attn_kernel(const float* __restrict__ qkv,
                            const float* __restrict__ rpb,
                            float* __restrict__ outp) {
    const int NTP = (NT == 64) ? 65 : 67;      // odd stride: conflict-free rows
    __shared__ float ks[NT][36];
    __shared__ float vs[NT][36];
    __shared__ float ss[NT][NTP];
    __shared__ float rpb_s[BIAS ? 225 : 1];

    int w = blockIdx.x, h = blockIdx.y;
    int row = threadIdx.x;

    float4 qv[8];
    {
        const float4* base = (const float4*)(qkv + ((size_t)w * NT + row) * 768 + h * 32);
        #pragma unroll
        for (int d4 = 0; d4 < 8; d4++) {
            float4 q = base[d4];
            qv[d4] = make_float4(q.x * SCALE, q.y * SCALE, q.z * SCALE, q.w * SCALE);
            float4 kk = base[64 + d4];     // +256 floats
            float4 vvv = base[128 + d4];   // +512 floats
            *(float4*)&ks[row][d4 * 4] = kk;
            *(float4*)&vs[row][d4 * 4] = vvv;
        }
    }
    if (BIAS) {
        for (int m = row; m < 225; m += NT) rpb_s[m] = rpb[m * HEADS + h];
    }
    __syncthreads();

    int yi = row >> 3, xi = row & 7;
    float mx = -1e30f;
    int j = 0;
    for (; j + 3 < NT; j += 4) {
        const float4* k0 = (const float4*)ks[j + 0];
        const float4* k1 = (const float4*)ks[j + 1];
        const float4* k2 = (const float4*)ks[j + 2];
        const float4* k3 = (const float4*)ks[j + 3];
        float s0 = 0.f, s1 = 0.f, s2 = 0.f, s3 = 0.f;
        #pragma unroll
        for (int d4 = 0; d4 < 8; d4++) {
            float4 q = qv[d4];
            s0 += dot4(q, k0[d4]);
            s1 += dot4(q, k1[d4]);
            s2 += dot4(q, k2[d4]);
            s3 += dot4(q, k3[d4]);
        }
        if (BIAS) {
            int bi = (yi + 7) * 15 + (xi + 7);
            s0 += rpb_s[bi - ((j + 0) >> 3) * 15 - ((j + 0) & 7)];
            s1 += rpb_s[bi - ((j + 1) >> 3) * 15 - ((j + 1) & 7)];
            s2 += rpb_s[bi - ((j + 2) >> 3) * 15 - ((j + 2) & 7)];
            s3 += rpb_s[bi - ((j + 3) >> 3) * 15 - ((j + 3) & 7)];
        }
        ss[row][j + 0] = s0; ss[row][j + 1] = s1;
        ss[row][j + 2] = s2; ss[row][j + 3] = s3;
        mx = fmaxf(mx, fmaxf(fmaxf(s0, s1), fmaxf(s2, s3)));
    }
    for (; j < NT; j++) {             // tail (NT=66)
        const float4* k0 = (const float4*)ks[j];
        float s0 = 0.f;
        #pragma unroll
        for (int d4 = 0; d4 < 8; d4++) s0 += dot4(qv[d4], k0[d4]);
        ss[row][j] = s0;
        mx = fmaxf(mx, s0);
    }

    float sum0 = 0.f, sum1 = 0.f;
    for (int jj = 0; jj + 1 < NT; jj += 2) {
        float e0 = __expf(ss[row][jj] - mx);
        float e1 = __expf(ss[row][jj + 1] - mx);
        ss[row][jj] = e0; ss[row][jj + 1] = e1;
        sum0 += e0; sum1 += e1;
    }
    if (NT & 1) { /* unreachable for 64/66 */ }
    float inv = 1.0f / (sum0 + sum1);

    float4 av[8];
    #pragma unroll
    for (int d4 = 0; d4 < 8; d4++) av[d4] = make_float4(0.f, 0.f, 0.f, 0.f);
    for (int jj = 0; jj + 1 < NT; jj += 2) {
        float p0 = ss[row][jj];
        float p1 = ss[row][jj + 1];
        const float4* v0 = (const float4*)vs[jj];
        const float4* v1 = (const float4*)vs[jj + 1];
        #pragma unroll
        for (int d4 = 0; d4 < 8; d4++) {
            float4 a = av[d4];
            float4 x0 = v0[d4], x1 = v1[d4];
            a.x += p0 * x0.x + p1 * x1.x;
            a.y += p0 * x0.y + p1 * x1.y;
            a.z += p0 * x0.z + p1 * x1.z;
            a.w += p0 * x0.w + p1 * x1.w;
            av[d4] = a;
        }
    }

    float4* ob = (float4*)(outp + ((size_t)w * NT + row) * CC + h * 32);
    #pragma unroll
    for (int d4 = 0; d4 < 8; d4++) {
        float4 a = av[d4];
        ob[d4] = make_float4(a.x * inv, a.y * inv, a.z * inv, a.w * inv);
    }
}

// ---------------------------------------------------------------------------
// Launch
// ---------------------------------------------------------------------------
extern "C" void kernel_launch(void* const* d_in, const int* in_sizes, int n_in,
                              void* d_out, int out_size) {
    (void)in_sizes; (void)n_in; (void)out_size;
    const float* x     = (const float*)d_in[0];
    const float* n1w   = (const float*)d_in[2];
    const float* n1b   = (const float*)d_in[3];
    const float* qkvw  = (const float*)d_in[4];
    const float* qkvb  = (const float*)d_in[5];
    const float* rpb   = (const float*)d_in[6];
    const float* projw = (const float*)d_in[7];
    const float* projb = (const float*)d_in[8];
    const float* n2w   = (const float*)d_in[9];
    const float* n2b   = (const float*)d_in[10];
    const float* fc1w  = (const float*)d_in[11];
    const float* fc1b  = (const float*)d_in[12];
    const float* fc2w  = (const float*)d_in[13];
    const float* fc2b  = (const float*)d_in[14];
    float* out = (float*)d_out;

    float *xln, *qkvs, *qkvf, *attn, *outf, *x2, *hln, *h1;
    cudaGetSymbolAddress((void**)&xln,  g_xln);
    cudaGetSymbolAddress((void**)&qkvs, g_qkvs);
    cudaGetSymbolAddress((void**)&qkvf, g_qkvf);
    cudaGetSymbolAddress((void**)&attn, g_attn);
    cudaGetSymbolAddress((void**)&outf, g_outf);
    cudaGetSymbolAddress((void**)&x2,   g_x2);
    cudaGetSymbolAddress((void**)&hln,  g_hln);
    cudaGetSymbolAddress((void**)&h1,   g_h1);

    cudaFuncSetAttribute(gemm_mma<0>, cudaFuncAttributeMaxDynamicSharedMemorySize, GEMM_SMEM);
    cudaFuncSetAttribute(gemm_mma<1>, cudaFuncAttributeMaxDynamicSharedMemorySize, GEMM_SMEM);
    cudaFuncSetAttribute(gemm_mma<2>, cudaFuncAttributeMaxDynamicSharedMemorySize, GEMM_SMEM);
    cudaFuncSetAttribute(gemm_mma<3>, cudaFuncAttributeMaxDynamicSharedMemorySize, GEMM_SMEM);

    init_dft_kernel<<<17, 256>>>();

    // LN1 (+ window partition)
    ln_kernel<<<TOKS, 256>>>(x, n1w, n1b, xln, 1);

    // spatial qkv: (131072 x 768)
    gemm_mma<0><<<dim3(768 / 256, TOKS / 128), 256, GEMM_SMEM>>>(
        xln, qkvw, qkvb, qkvs, TOKS, 768, 256, nullptr);

    // spectral qkv via DFT of spatial qkv (linearity)
    spec_qkv_kernel<<<dim3(NWIN, 3), 256>>>(qkvs, qkvb, qkvf);

    // attention
    attn_kernel<NTOK, true ><<<dim3(NWIN, HEADS), NTOK>>>(qkvs, rpb, attn);
    attn_kernel<NF,   false><<<dim3(NWIN, HEADS), NF  >>>(qkvf, nullptr, outf);

    // irfft of spectral branch -> accumulate into spatial attn output
    ifft_acc_kernel<<<NWIN, 256>>>(outf, attn);

    // proj + window reverse + shortcut -> x2
    gemm_mma<3><<<dim3(256 / 256, TOKS / 128), 256, GEMM_SMEM>>>(
        attn, projw, projb, x2, TOKS, 256, 256, x);

    // LN2
    ln_kernel<<<TOKS, 256>>>(x2, n2w, n2b, hln, 0);

    // fc1 + GELU
    gemm_mma<1><<<dim3(1024 / 256, TOKS / 128), 256, GEMM_SMEM>>>(
        hln, fc1w, fc1b, h1, TOKS, 1024, 256, nullptr);

    // fc2 + residual -> out
    gemm_mma<2><<<dim3(256 / 256, TOKS / 128), 256, GEMM_SMEM>>>(
        h1, fc2w, fc2b, out, TOKS, 256, 1024, x2);
}

// round 7
// speedup vs baseline: 3.1062x; 1.0686x over previous
#include <cuda_runtime.h>
#include <math.h>
#include <stdint.h>

// ---------------------------------------------------------------------------
// Problem constants
// ---------------------------------------------------------------------------
#define CC      256
#define WS      8
#define NTOK    64
#define NF      66
#define HEADS   8
#define HD      32
#define NWIN    2048
#define TOKS    131072
#define SCALE   0.17677669529663687f

// ---------------------------------------------------------------------------
// Scratch
// ---------------------------------------------------------------------------
__device__ float g_xln [ (size_t)NWIN * NTOK * CC ];
__device__ float g_qkvs[ (size_t)NWIN * NTOK * 3 * CC ];
__device__ float g_qkvf[ (size_t)NWIN * NF   * 3 * CC ];
__device__ float g_attn[ (size_t)NWIN * NTOK * CC ];
__device__ float g_outf[ (size_t)NWIN * NF   * CC ];
__device__ float g_x2  [ (size_t)TOKS * CC ];
__device__ float g_hln [ (size_t)TOKS * CC ];
__device__ float g_h1  [ (size_t)TOKS * 4 * CC ];
// Half-size symmetry-folded DFT matrices (33 rows x 34-padded cols)
__device__ float g_Fc[ 33 * 34 ];
__device__ float g_Fs[ 33 * 34 ];
__device__ float g_Ic[ 33 * 34 ];
__device__ float g_Is[ 33 * 34 ];

// ---------------------------------------------------------------------------
// Helpers
// ---------------------------------------------------------------------------
__device__ __forceinline__ uint32_t smem_u32(const void* p) {
    uint32_t a;
    asm("{ .reg .u64 t; cvta.to.shared.u64 t, %1; cvt.u32.u64 %0, t; }"
        : "=r"(a) : "l"(p));
    return a;
}

#define CP_ASYNC16(dst_u32, src_ptr) \
    asm volatile("cp.async.cg.shared.global [%0], [%1], 16;" \
        :: "r"(dst_u32), "l"(src_ptr))
#define CP_COMMIT() asm volatile("cp.async.commit_group;")
#define CP_WAIT1()  asm volatile("cp.async.wait_group 1;")
#define CP_WAIT0()  asm volatile("cp.async.wait_group 0;")

__device__ __forceinline__ void mma16n8k8(float* c, const uint32_t* a,
                                          const uint32_t* b) {
    asm volatile(
        "mma.sync.aligned.m16n8k8.row.col.f32.tf32.tf32.f32 "
        "{%0,%1,%2,%3}, {%4,%5,%6,%7}, {%8,%9}, {%0,%1,%2,%3};"
        : "+f"(c[0]), "+f"(c[1]), "+f"(c[2]), "+f"(c[3])
        : "r"(a[0]), "r"(a[1]), "r"(a[2]), "r"(a[3]), "r"(b[0]), "r"(b[1]));
}

__device__ __forceinline__ int win2pix(int t) {
    int b   = t >> 16;
    int rem = t & 65535;
    int wl  = rem >> 6;
    int n   = rem & 63;
    int wh  = wl >> 5, ww = wl & 31;
    int i   = n >> 3,  j  = n & 7;
    return (b * 256 + wh * 8 + i) * 256 + (ww * 8 + j);
}

__device__ __forceinline__ float dot4(float4 a, float4 b) {
    return a.x * b.x + a.y * b.y + a.z * b.z + a.w * b.w;
}

// ---------------------------------------------------------------------------
// Symmetry-folded DFT matrix init
//   forward:  xc[f] = sum_{n=0..32} Fc[f][n]*e[n]       (e[n]=x[n]+x[64-n], e0=x0, e32=x32)
//             xs[f'] = sum_{n=1..31} Fs[f'][n]*o[n]     (o[n]=x[n]-x[64-n])
//   inverse:  a[n] = sum_{r=0..32} Ic[n][r]*fr[r];  b[n] = sum_{r'=1..31} Is[n][r']*fr[33+r']
//             out[n]=a+b, out[64-n]=a-b
// ---------------------------------------------------------------------------
__global__ void init_dft_kernel() {
    int i = blockIdx.x * blockDim.x + threadIdx.x;
    if (i < 33 * 34) {
        int r = i / 34, c = i % 34;
        float fc = 0.f, fs = 0.f, ic = 0.f, is = 0.f;
        if (c < 33) {
            float cs = cospif((float)(r * c) / 32.0f);
            float sn = sinpif((float)(r * c) / 32.0f);
            fc = 0.125f * cs;
            fs = -0.125f * sn;
            if (c == 0)       ic = 0.125f;
            else if (c == 32) ic = 0.125f * cospif((float)r);
            else              ic = 0.25f * cs;
            is = -0.25f * sn;
        }
        g_Fc[i] = fc; g_Fs[i] = fs; g_Ic[i] = ic; g_Is[i] = is;
    }
}

// ---------------------------------------------------------------------------
// LayerNorm
// ---------------------------------------------------------------------------
__global__ void ln_kernel(const float* __restrict__ xin,
                          const float* __restrict__ w,
                          const float* __restrict__ b,
                          float* __restrict__ out, int winmap) {
    __shared__ float red[16];
    int t = blockIdx.x, c = threadIdx.x;
    int rin = winmap ? win2pix(t) : t;
    float v = xin[(size_t)rin * CC + c];
    float s = v, sq = v * v;
    #pragma unroll
    for (int o = 16; o; o >>= 1) {
        s  += __shfl_down_sync(0xffffffffu, s,  o);
        sq += __shfl_down_sync(0xffffffffu, sq, o);
    }
    int warp = c >> 5, lane = c & 31;
    if (lane == 0) { red[warp] = s; red[8 + warp] = sq; }
    __syncthreads();
    if (c == 0) {
        float S = 0.f, Q = 0.f;
        #pragma unroll
        for (int i = 0; i < 8; i++) { S += red[i]; Q += red[8 + i]; }
        red[0] = S * (1.0f / CC);
        red[8] = Q * (1.0f / CC);
    }
    __syncthreads();
    float mean = red[0];
    float var  = red[8] - mean * mean;
    out[(size_t)t * CC + c] = (v - mean) * rsqrtf(var + 1e-5f) * w[c] + b[c];
}

// ---------------------------------------------------------------------------
// tf32 mma.sync GEMM, 3-stage cp.async pipeline, one sync per K-chunk.
// 128x256 CTA tile, BK=32, 8 warps (2x4), warp tile 64x64.
// EPI: 0 plain, 1 GELU, 2 +res[m*N+n], 3 window-reverse +res
// ---------------------------------------------------------------------------
#define SMS 36
#define A_STAGE (128 * SMS)
#define B_STAGE (256 * SMS)
#define GEMM_SMEM (3 * (A_STAGE + B_STAGE) * 4)

template<int EPI>
__global__ __launch_bounds__(256, 1)
void gemm_mma(const float* __restrict__ A, const float* __restrict__ W,
              const float* __restrict__ bias, float* __restrict__ C,
              int M, int N, int K, const float* __restrict__ res) {
    extern __shared__ float sm[];
    float* AsBase = sm;                      // [3][128][SMS]
    float* BsBase = sm + 3 * A_STAGE;        // [3][256][SMS]
    uint32_t sA = smem_u32(AsBase);
    uint32_t sB = smem_u32(BsBase);

    int tid = threadIdx.x;
    int m0 = blockIdx.y * 128, n0 = blockIdx.x * 256;
    int wid = tid >> 5, lane = tid & 31;
    int wm = (wid & 1) * 64, wn = (wid >> 1) * 64;
    int grp = lane >> 2, tg = lane & 3;

    float acc[4][8][4];
    #pragma unroll
    for (int a = 0; a < 4; a++)
        #pragma unroll
        for (int b = 0; b < 8; b++)
            #pragma unroll
            for (int c = 0; c < 4; c++) acc[a][b][c] = 0.f;

    const int NC = K / 32;

    // prologue: chunks 0,1 -> stages 0,1
    #pragma unroll
    for (int pc = 0; pc < 2; pc++) {
        #pragma unroll
        for (int t = 0; t < 4; t++) {
            int idx = tid + t * 256;
            int row = idx >> 3, q = idx & 7;
            CP_ASYNC16(sA + (uint32_t)(pc * A_STAGE + row * SMS + q * 4) * 4u,
                       A + (size_t)(m0 + row) * K + pc * 32 + q * 4);
        }
        #pragma unroll
        for (int t = 0; t < 8; t++) {
            int idx = tid + t * 256;
            int row = idx >> 3, q = idx & 7;
            CP_ASYNC16(sB + (uint32_t)(pc * B_STAGE + row * SMS + q * 4) * 4u,
                       W + (size_t)(n0 + row) * K + pc * 32 + q * 4);
        }
        CP_COMMIT();
    }

    for (int i = 0; i < NC; i++) {
        if (i + 1 < NC) CP_WAIT1(); else CP_WAIT0();
        __syncthreads();
        if (i + 2 < NC) {
            int st = (i + 2) % 3;
            #pragma unroll
            for (int t = 0; t < 4; t++) {
                int idx = tid + t * 256;
                int row = idx >> 3, q = idx & 7;
                CP_ASYNC16(sA + (uint32_t)(st * A_STAGE + row * SMS + q * 4) * 4u,
                           A + (size_t)(m0 + row) * K + (i + 2) * 32 + q * 4);
            }
            #pragma unroll
            for (int t = 0; t < 8; t++) {
                int idx = tid + t * 256;
                int row = idx >> 3, q = idx & 7;
                CP_ASYNC16(sB + (uint32_t)(st * B_STAGE + row * SMS + q * 4) * 4u,
                           W + (size_t)(n0 + row) * K + (i + 2) * 32 + q * 4);
            }
            CP_COMMIT();
        }

        const float* As = AsBase + (i % 3) * A_STAGE;
        const float* Bs = BsBase + (i % 3) * B_STAGE;
        #pragma unroll
        for (int ks = 0; ks < 4; ks++) {
            uint32_t af[4][4];
            uint32_t bf[8][2];
            #pragma unroll
            for (int mi = 0; mi < 4; mi++) {
                int r = wm + mi * 16 + grp;
                af[mi][0] = __float_as_uint(As[r * SMS + ks * 8 + tg]);
                af[mi][1] = __float_as_uint(As[(r + 8) * SMS + ks * 8 + tg]);
                af[mi][2] = __float_as_uint(As[r * SMS + ks * 8 + tg + 4]);
                af[mi][3] = __float_as_uint(As[(r + 8) * SMS + ks * 8 + tg + 4]);
            }
            #pragma unroll
            for (int ni = 0; ni < 8; ni++) {
                int r = wn + ni * 8 + grp;
                bf[ni][0] = __float_as_uint(Bs[r * SMS + ks * 8 + tg]);
                bf[ni][1] = __float_as_uint(Bs[r * SMS + ks * 8 + tg + 4]);
            }
            #pragma unroll
            for (int mi = 0; mi < 4; mi++)
                #pragma unroll
                for (int ni = 0; ni < 8; ni++)
                    mma16n8k8(acc[mi][ni], af[mi], bf[ni]);
        }
    }

    #pragma unroll
    for (int mi = 0; mi < 4; mi++) {
        #pragma unroll
        for (int half = 0; half < 2; half++) {
            int m = m0 + wm + mi * 16 + grp + half * 8;
            size_t orow = (EPI == 3) ? (size_t)win2pix(m) * N : (size_t)m * N;
            #pragma unroll
            for (int ni = 0; ni < 8; ni++) {
                int n = n0 + wn + ni * 8 + tg * 2;
                float vx = acc[mi][ni][half * 2 + 0] + bias[n];
                float vy = acc[mi][ni][half * 2 + 1] + bias[n + 1];
                if (EPI == 1) {
                    vx = 0.5f * vx * (1.0f + erff(vx * 0.7071067811865476f));
                    vy = 0.5f * vy * (1.0f + erff(vy * 0.7071067811865476f));
                } else if (EPI == 2) {
                    vx += res[(size_t)m * N + n];
                    vy += res[(size_t)m * N + n + 1];
                } else if (EPI == 3) {
                    vx += res[orow + n];
                    vy += res[orow + n + 1];
                }
                *(float2*)(C + orow + n) = make_float2(vx, vy);
            }
        }
    }
}

// ---------------------------------------------------------------------------
// Fused spectral qkv with cos/sin symmetry (half the FMAs).
// qkvf[w,f,ch] = (F @ qkvs[w])[f,ch] + bias correction.
// ---------------------------------------------------------------------------
__global__ __launch_bounds__(256)
void spec_qkv_kernel(const float* __restrict__ qkvs,
                     const float* __restrict__ qkvb,
                     float* __restrict__ qkvf) {
    __shared__ float Fc[33 * 34];
    __shared__ float Fs[33 * 34];
    int w = blockIdx.x;
    int tid = threadIdx.x;
    int ch = blockIdx.y * 256 + tid;
    for (int m = tid; m < 33 * 34; m += 256) { Fc[m] = g_Fc[m]; Fs[m] = g_Fs[m]; }

    float e[33], o[32];
    const float* src = qkvs + (size_t)w * NTOK * 768 + ch;
    e[0]  = src[0];
    e[32] = src[(size_t)32 * 768];
    #pragma unroll
    for (int n = 1; n < 32; n++) {
        float a = src[(size_t)n * 768];
        float b = src[(size_t)(64 - n) * 768];
        e[n] = a + b;
        o[n] = a - b;
    }
    __syncthreads();

    float bb = qkvb[ch];
    float* dst = qkvf + (size_t)w * NF * 768 + ch;

    // cos rows f = 0..32 (pairs + tail)
    #pragma unroll 1
    for (int f = 0; f < 32; f += 2) {
        const float* R0 = Fc + f * 34;
        const float* R1 = R0 + 34;
        float s0 = 0.f, s0b = 0.f, s1 = 0.f, s1b = 0.f;
        #pragma unroll
        for (int n = 0; n < 32; n += 2) {
            s0  += R0[n] * e[n];     s0b += R0[n + 1] * e[n + 1];
            s1  += R1[n] * e[n];     s1b += R1[n + 1] * e[n + 1];
        }
        s0 += R0[32] * e[32];
        s1 += R1[32] * e[32];
        dst[(size_t)f * 768]       = s0 + s0b + ((f == 0) ? -7.0f * bb : bb);
        dst[(size_t)(f + 1) * 768] = s1 + s1b + bb;
    }
    {
        const float* R0 = Fc + 32 * 34;
        float s0 = 0.f, s0b = 0.f;
        #pragma unroll
        for (int n = 0; n < 32; n += 2) {
            s0 += R0[n] * e[n]; s0b += R0[n + 1] * e[n + 1];
        }
        s0 += R0[32] * e[32];
        dst[(size_t)32 * 768] = s0 + s0b + bb;
    }

    // imag DC / Nyquist rows are exactly zero -> just the bias
    dst[(size_t)33 * 768] = bb;
    dst[(size_t)65 * 768] = bb;

    // sin rows f' = 1..31 -> output rows 33+f' (pairs + tail)
    #pragma unroll 1
    for (int f = 1; f < 31; f += 2) {
        const float* R0 = Fs + f * 34;
        const float* R1 = R0 + 34;
        float s0 = 0.f, s0b = 0.f, s1 = 0.f, s1b = 0.f;
        #pragma unroll
        for (int n = 1; n < 31; n += 2) {
            s0  += R0[n] * o[n];     s0b += R0[n + 1] * o[n + 1];
            s1  += R1[n] * o[n];     s1b += R1[n + 1] * o[n + 1];
        }
        s0 += R0[31] * o[31];
        s1 += R1[31] * o[31];
        dst[(size_t)(33 + f) * 768] = s0 + s0b + bb;
        dst[(size_t)(34 + f) * 768] = s1 + s1b + bb;
    }
    {
        const float* R0 = Fs + 31 * 34;
        float s0 = 0.f, s0b = 0.f;
        #pragma unroll
        for (int n = 1; n < 31; n += 2) {
            s0 += R0[n] * o[n]; s0b += R0[n + 1] * o[n + 1];
        }
        s0 += R0[31] * o[31];
        dst[(size_t)64 * 768] = s0 + s0b + bb;
    }
}

// ---------------------------------------------------------------------------
// Inverse rfft accumulate with symmetry: out[n]=a+b, out[64-n]=a-b.
// ---------------------------------------------------------------------------
__global__ __launch_bounds__(256)
void ifft_acc_kernel(const float* __restrict__ outf,
                     float* __restrict__ acc) {
    __shared__ float Ic[33 * 34];
    __shared__ float Is[33 * 34];
    int w = blockIdx.x;
    int c = threadIdx.x;
    for (int m = c; m < 33 * 34; m += 256) { Ic[m] = g_Ic[m]; Is[m] = g_Is[m]; }

    float fr[NF];
    const float* src = outf + (size_t)w * NF * CC + c;
    #pragma unroll 11
    for (int r = 0; r < NF; r++) fr[r] = src[(size_t)r * CC];
    __syncthreads();

    float* dst = acc + (size_t)w * NTOK * CC + c;
    #pragma unroll 1
    for (int n = 0; n < 32; n += 2) {
        const float* C0 = Ic + n * 34;
        const float* C1 = C0 + 34;
        const float* S0 = Is + n * 34;
        const float* S1 = S0 + 34;
        float a0 = 0.f, a0b = 0.f, a1 = 0.f, a1b = 0.f;
        #pragma unroll
        for (int r = 0; r < 32; r += 2) {
            a0  += C0[r] * fr[r];     a0b += C0[r + 1] * fr[r + 1];
            a1  += C1[r] * fr[r];     a1b += C1[r + 1] * fr[r + 1];
        }
        a0 += C0[32] * fr[32];
        a1 += C1[32] * fr[32];
        float b0 = 0.f, b0b = 0.f, b1 = 0.f, b1b = 0.f;
        #pragma unroll
        for (int r = 1; r < 31; r += 2) {
            b0  += S0[r] * fr[33 + r];     b0b += S0[r + 1] * fr[34 + r];
            b1  += S1[r] * fr[33 + r];     b1b += S1[r + 1] * fr[34 + r];
        }
        b0 += S0[31] * fr[64];
        b1 += S1[31] * fr[64];
        float A0 = a0 + a0b, B0 = b0 + b0b;
        float A1 = a1 + a1b, B1 = b1 + b1b;
        dst[(size_t)n * CC] += A0 + B0;
        if (n >= 1) dst[(size_t)(64 - n) * CC] += A0 - B0;       // n even>=2 handled; n=0 no mirror
        dst[(size_t)(n + 1) * CC] += A1 + B1;
        dst[(size_t)(63 - n) * CC] += A1 - B1;                   // mirror of n+1
    }
    {   // n = 32 (self-paired, sin part zero)
        const float* C0 = Ic + 32 * 34;
        float a0 = 0.f, a0b = 0.f;
        #pragma unroll
        for (int r = 0; r < 32; r += 2) {
            a0 += C0[r] * fr[r]; a0b += C0[r + 1] * fr[r + 1];
        }
        a0 += C0[32] * fr[32];
        dst[(size_t)32 * CC] += a0 + a0b;
    }
}

// ---------------------------------------------------------------------------
// Spatial window attention (unchanged from R6): block (w, h), 64 threads.
// ---------------------------------------------------------------------------
template<int NT, bool BIAS>
__global__ void attn_kernel(const float* __restrict__ qkv,
                            const float* __restrict__ rpb,
                            float* __restrict__ outp) {
    const int NTP = (NT == 64) ? 65 : 67;
    __shared__ float ks[NT][36];
    __shared__ float vs[NT][36];
    __shared__ float ss[NT][NTP];
    __shared__ float rpb_s[BIAS ? 225 : 1];

    int w = blockIdx.x, h = blockIdx.y;
    int row = threadIdx.x;

    float4 qv[8];
    {
        const float4* base = (const float4*)(qkv + ((size_t)w * NT + row) * 768 + h * 32);
        #pragma unroll
        for (int d4 = 0; d4 < 8; d4++) {
            float4 q = base[d4];
            qv[d4] = make_float4(q.x * SCALE, q.y * SCALE, q.z * SCALE, q.w * SCALE);
            *(float4*)&ks[row][d4 * 4] = base[64 + d4];
            *(float4*)&vs[row][d4 * 4] = base[128 + d4];
        }
    }
    if (BIAS) {
        for (int m = row; m < 225; m += NT) rpb_s[m] = rpb[m * HEADS + h];
    }
    __syncthreads();

    int yi = row >> 3, xi = row & 7;
    float mx = -1e30f;
    int j = 0;
    for (; j + 3 < NT; j += 4) {
        const float4* k0 = (const float4*)ks[j + 0];
        const float4* k1 = (const float4*)ks[j + 1];
        const float4* k2 = (const float4*)ks[j + 2];
        const float4* k3 = (const float4*)ks[j + 3];
        float s0 = 0.f, s1 = 0.f, s2 = 0.f, s3 = 0.f;
        #pragma unroll
        for (int d4 = 0; d4 < 8; d4++) {
            float4 q = qv[d4];
            s0 += dot4(q, k0[d4]);
            s1 += dot4(q, k1[d4]);
            s2 += dot4(q, k2[d4]);
            s3 += dot4(q, k3[d4]);
        }
        if (BIAS) {
            int bi = (yi + 7) * 15 + (xi + 7);
            s0 += rpb_s[bi - ((j + 0) >> 3) * 15 - ((j + 0) & 7)];
            s1 += rpb_s[bi - ((j + 1) >> 3) * 15 - ((j + 1) & 7)];
            s2 += rpb_s[bi - ((j + 2) >> 3) * 15 - ((j + 2) & 7)];
            s3 += rpb_s[bi - ((j + 3) >> 3) * 15 - ((j + 3) & 7)];
        }
        ss[row][j + 0] = s0; ss[row][j + 1] = s1;
        ss[row][j + 2] = s2; ss[row][j + 3] = s3;
        mx = fmaxf(mx, fmaxf(fmaxf(s0, s1), fmaxf(s2, s3)));
    }
    for (; j < NT; j++) {
        const float4* k0 = (const float4*)ks[j];
        float s0 = 0.f;
        #pragma unroll
        for (int d4 = 0; d4 < 8; d4++) s0 += dot4(qv[d4], k0[d4]);
        ss[row][j] = s0;
        mx = fmaxf(mx, s0);
    }

    float sum0 = 0.f, sum1 = 0.f;
    for (int jj = 0; jj + 1 < NT; jj += 2) {
        float e0 = __expf(ss[row][jj] - mx);
        float e1 = __expf(ss[row][jj + 1] - mx);
        ss[row][jj] = e0; ss[row][jj + 1] = e1;
        sum0 += e0; sum1 += e1;
    }
    float inv = 1.0f / (sum0 + sum1);

    float4 av[8];
    #pragma unroll
    for (int d4 = 0; d4 < 8; d4++) av[d4] = make_float4(0.f, 0.f, 0.f, 0.f);
    for (int jj = 0; jj + 1 < NT; jj += 2) {
        float p0 = ss[row][jj];
        float p1 = ss[row][jj + 1];
        const float4* v0 = (const float4*)vs[jj];
        const float4* v1 = (const float4*)vs[jj + 1];
        #pragma unroll
        for (int d4 = 0; d4 < 8; d4++) {
            float4 a = av[d4];
            float4 x0 = v0[d4], x1 = v1[d4];
            a.x += p0 * x0.x + p1 * x1.x;
            a.y += p0 * x0.y + p1 * x1.y;
            a.z += p0 * x0.z + p1 * x1.z;
            a.w += p0 * x0.w + p1 * x1.w;
            av[d4] = a;
        }
    }

    float4* ob = (float4*)(outp + ((size_t)w * NT + row) * CC + h * 32);
    #pragma unroll
    for (int d4 = 0; d4 < 8; d4++) {
        float4 a = av[d4];
        ob[d4] = make_float4(a.x * inv, a.y * inv, a.z * inv, a.w * inv);
    }
}

// ---------------------------------------------------------------------------
// Spectral attention: 2 windows per block (132 of 160 lanes active).
// ---------------------------------------------------------------------------
__global__ __launch_bounds__(160)
void attn_spec2_kernel(const float* __restrict__ qkv,
                       float* __restrict__ outp) {
    __shared__ float ks[2][NF][36];
    __shared__ float vs[2][NF][36];
    __shared__ float ss[2][NF][67];

    int w2 = blockIdx.x, h = blockIdx.y;
    int tid = threadIdx.x;
    int sub = tid / NF;          // 0 or 1 (>=2 -> inactive)
    int row = tid % NF;
    bool act = tid < 2 * NF;
    int w = w2 * 2 + sub;

    float4 qv[8];
    if (act) {
        const float4* base = (const float4*)(qkv + ((size_t)w * NF + row) * 768 + h * 32);
        #pragma unroll
        for (int d4 = 0; d4 < 8; d4++) {
            float4 q = base[d4];
            qv[d4] = make_float4(q.x * SCALE, q.y * SCALE, q.z * SCALE, q.w * SCALE);
            *(float4*)&ks[sub][row][d4 * 4] = base[64 + d4];
            *(float4*)&vs[sub][row][d4 * 4] = base[128 + d4];
        }
    }
    __syncthreads();
    if (!act) return;

    float mx = -1e30f;
    int j = 0;
    for (; j + 3 < NF; j += 4) {
        const float4* k0 = (const float4*)ks[sub][j + 0];
        const float4* k1 = (const float4*)ks[sub][j + 1];
        const float4* k2 = (const float4*)ks[sub][j + 2];
        const float4* k3 = (const float4*)ks[sub][j + 3];
        float s0 = 0.f, s1 = 0.f, s2 = 0.f, s3 = 0.f;
        #pragma unroll
        for (int d4 = 0; d4 < 8; d4++) {
            float4 q = qv[d4];
            s0 += dot4(q, k0[d4]);
            s1 += dot4(q, k1[d4]);
            s2 += dot4(q, k2[d4]);
            s3 += dot4(q, k3[d4]);
        }
        ss[sub][row][j + 0] = s0; ss[sub][row][j + 1] = s1;
        ss[sub][row][j + 2] = s2; ss[sub][row][j + 3] = s3;
        mx = fmaxf(mx, fmaxf(fmaxf(s0, s1), fmaxf(s2, s3)));
    }
    for (; j < NF; j++) {
        const float4* k0 = (const float4*)ks[sub][j];
        float s0 = 0.f;
        #pragma unroll
        for (int d4 = 0; d4 < 8; d4++) s0 += dot4(qv[d4], k0[d4]);
        ss[sub][row][j] = s0;
        mx = fmaxf(mx, s0);
    }

    float sum0 = 0.f, sum1 = 0.f;
    for (int jj = 0; jj + 1 < NF; jj += 2) {
        float e0 = __expf(ss[sub][row][jj] - mx);
        float e1 = __expf(ss[sub][row][jj + 1] - mx);
        ss[sub][row][jj] = e0; ss[sub][row][jj + 1] = e1;
        sum0 += e0; sum1 += e1;
    }
    float inv = 1.0f / (sum0 + sum1);

    float4 av[8];
    #pragma unroll
    for (int d4 = 0; d4 < 8; d4++) av[d4] = make_float4(0.f, 0.f, 0.f, 0.f);
    for (int jj = 0; jj + 1 < NF; jj += 2) {
        float p0 = ss[sub][row][jj];
        float p1 = ss[sub][row][jj + 1];
        const float4* v0 = (const float4*)vs[sub][jj];
        const float4* v1 = (const float4*)vs[sub][jj + 1];
        #pragma unroll
        for (int d4 = 0; d4 < 8; d4++) {
            float4 a = av[d4];
            float4 x0 = v0[d4], x1 = v1[d4];
            a.x += p0 * x0.x + p1 * x1.x;
            a.y += p0 * x0.y + p1 * x1.y;
            a.z += p0 * x0.z + p1 * x1.z;
            a.w += p0 * x0.w + p1 * x1.w;
            av[d4] = a;
        }
    }

    float4* ob = (float4*)(outp + ((size_t)w * NF + row) * CC + h * 32);
    #pragma unroll
    for (int d4 = 0; d4 < 8; d4++) {
        float4 a = av[d4];
        ob[d4] = make_float4(a.x * inv, a.y * inv, a.z * inv, a.w * inv);
    }
}

// ---------------------------------------------------------------------------
// Launch
// ---------------------------------------------------------------------------
extern "C" void kernel_launch(void* const* d_in, const int* in_sizes, int n_in,
                              void* d_out, int out_size) {
    (void)in_sizes; (void)n_in; (void)out_size;
    const float* x     = (const float*)d_in[0];
    const float* n1w   = (const float*)d_in[2];
    const float* n1b   = (const float*)d_in[3];
    const float* qkvw  = (const float*)d_in[4];
    const float* qkvb  = (const float*)d_in[5];
    const float* rpb   = (const float*)d_in[6];
    const float* projw = (const float*)d_in[7];
    const float* projb = (const float*)d_in[8];
    const float* n2w   = (const float*)d_in[9];
    const float* n2b   = (const float*)d_in[10];
    const float* fc1w  = (const float*)d_in[11];
    const float* fc1b  = (const float*)d_in[12];
    const float* fc2w  = (const float*)d_in[13];
    const float* fc2b  = (const float*)d_in[14];
    float* out = (float*)d_out;

    float *xln, *qkvs, *qkvf, *attn, *outf, *x2, *hln, *h1;
    cudaGetSymbolAddress((void**)&xln,  g_xln);
    cudaGetSymbolAddress((void**)&qkvs, g_qkvs);
    cudaGetSymbolAddress((void**)&qkvf, g_qkvf);
    cudaGetSymbolAddress((void**)&attn, g_attn);
    cudaGetSymbolAddress((void**)&outf, g_outf);
    cudaGetSymbolAddress((void**)&x2,   g_x2);
    cudaGetSymbolAddress((void**)&hln,  g_hln);
    cudaGetSymbolAddress((void**)&h1,   g_h1);

    cudaFuncSetAttribute(gemm_mma<0>, cudaFuncAttributeMaxDynamicSharedMemorySize, GEMM_SMEM);
    cudaFuncSetAttribute(gemm_mma<1>, cudaFuncAttributeMaxDynamicSharedMemorySize, GEMM_SMEM);
    cudaFuncSetAttribute(gemm_mma<2>, cudaFuncAttributeMaxDynamicSharedMemorySize, GEMM_SMEM);
    cudaFuncSetAttribute(gemm_mma<3>, cudaFuncAttributeMaxDynamicSharedMemorySize, GEMM_SMEM);

    init_dft_kernel<<<5, 256>>>();

    // LN1 (+ window partition)
    ln_kernel<<<TOKS, 256>>>(x, n1w, n1b, xln, 1);

    // spatial qkv: (131072 x 768)
    gemm_mma<0><<<dim3(768 / 256, TOKS / 128), 256, GEMM_SMEM>>>(
        xln, qkvw, qkvb, qkvs, TOKS, 768, 256, nullptr);

    // spectral qkv via DFT of spatial qkv (linearity + cos/sin symmetry)
    spec_qkv_kernel<<<dim3(NWIN, 3), 256>>>(qkvs, qkvb, qkvf);

    // attention
    attn_kernel<NTOK, true><<<dim3(NWIN, HEADS), NTOK>>>(qkvs, rpb, attn);
    attn_spec2_kernel<<<dim3(NWIN / 2, HEADS), 160>>>(qkvf, outf);

    // irfft of spectral branch -> accumulate into spatial attn output
    ifft_acc_kernel<<<NWIN, 256>>>(outf, attn);

    // proj + window reverse + shortcut -> x2
    gemm_mma<3><<<dim3(256 / 256, TOKS / 128), 256, GEMM_SMEM>>>(
        attn, projw, projb, x2, TOKS, 256, 256, x);

    // LN2
    ln_kernel<<<TOKS, 256>>>(x2, n2w, n2b, hln, 0);

    // fc1 + GELU
    gemm_mma<1><<<dim3(1024 / 256, TOKS / 128), 256, GEMM_SMEM>>>(
        hln, fc1w, fc1b, h1, TOKS, 1024, 256, nullptr);

    // fc2 + residual -> out
    gemm_mma<2><<<dim3(256 / 256, TOKS / 128), 256, GEMM_SMEM>>>(
        h1, fc2w, fc2b, out, TOKS, 256, 1024, x2);
}

// round 9
// speedup vs baseline: 3.5202x; 1.1333x over previous
#include <cuda_runtime.h>
#include <cuda_bf16.h>
#include <math.h>
#include <stdint.h>

// ---------------------------------------------------------------------------
// Problem constants
// ---------------------------------------------------------------------------
#define CC      256
#define WS      8
#define NTOK    64
#define NF      66
#define HEADS   8
#define HD      32
#define NWIN    2048
#define TOKS    131072
#define SCALE   0.17677669529663687f

// ---------------------------------------------------------------------------
// Scratch
// ---------------------------------------------------------------------------
__device__ float g_xln [ (size_t)NWIN * NTOK * CC ];
__device__ float g_qkvs[ (size_t)NWIN * NTOK * 3 * CC ];
__device__ float g_qkvf[ (size_t)NWIN * NF   * 3 * CC ];
__device__ float g_attn[ (size_t)NWIN * NTOK * CC ];
__device__ float g_outf[ (size_t)NWIN * NF   * CC ];
__device__ float g_x2  [ (size_t)TOKS * CC ];
__device__ __nv_bfloat16 g_hln[ (size_t)TOKS * CC ];          // LN2 out (bf16)
__device__ __nv_bfloat16 g_h1 [ (size_t)TOKS * 4 * CC ];      // fc1+gelu out (bf16)
__device__ __nv_bfloat16 g_w1bf[ 1024 * 256 ];
__device__ __nv_bfloat16 g_w2bf[ 256 * 1024 ];
// Half-size symmetry-folded DFT matrices (33 rows x 34-padded cols)
__device__ float g_Fc[ 33 * 34 ];
__device__ float g_Fs[ 33 * 34 ];
__device__ float g_Ic[ 33 * 34 ];
__device__ float g_Is[ 33 * 34 ];

// ---------------------------------------------------------------------------
// Helpers
// ---------------------------------------------------------------------------
__device__ __forceinline__ uint32_t smem_u32(const void* p) {
    uint32_t a;
    asm("{ .reg .u64 t; cvta.to.shared.u64 t, %1; cvt.u32.u64 %0, t; }"
        : "=r"(a) : "l"(p));
    return a;
}

#define CP_ASYNC16(dst_u32, src_ptr) \
    asm volatile("cp.async.cg.shared.global [%0], [%1], 16;" \
        :: "r"(dst_u32), "l"(src_ptr))
#define CP_COMMIT() asm volatile("cp.async.commit_group;")
#define CP_WAIT1()  asm volatile("cp.async.wait_group 1;")
#define CP_WAIT0()  asm volatile("cp.async.wait_group 0;")

__device__ __forceinline__ void mma16n8k8(float* c, const uint32_t* a,
                                          const uint32_t* b) {
    asm volatile(
        "mma.sync.aligned.m16n8k8.row.col.f32.tf32.tf32.f32 "
        "{%0,%1,%2,%3}, {%4,%5,%6,%7}, {%8,%9}, {%0,%1,%2,%3};"
        : "+f"(c[0]), "+f"(c[1]), "+f"(c[2]), "+f"(c[3])
        : "r"(a[0]), "r"(a[1]), "r"(a[2]), "r"(a[3]), "r"(b[0]), "r"(b[1]));
}

__device__ __forceinline__ void mma16n8k16bf(float* c, const uint32_t* a,
                                             const uint32_t* b) {
    asm volatile(
        "mma.sync.aligned.m16n8k16.row.col.f32.bf16.bf16.f32 "
        "{%0,%1,%2,%3}, {%4,%5,%6,%7}, {%8,%9}, {%0,%1,%2,%3};"
        : "+f"(c[0]), "+f"(c[1]), "+f"(c[2]), "+f"(c[3])
        : "r"(a[0]), "r"(a[1]), "r"(a[2]), "r"(a[3]), "r"(b[0]), "r"(b[1]));
}

__device__ __forceinline__ int win2pix(int t) {
    int b   = t >> 16;
    int rem = t & 65535;
    int wl  = rem >> 6;
    int n   = rem & 63;
    int wh  = wl >> 5, ww = wl & 31;
    int i   = n >> 3,  j  = n & 7;
    return (b * 256 + wh * 8 + i) * 256 + (ww * 8 + j);
}

__device__ __forceinline__ float dot4(float4 a, float4 b) {
    return a.x * b.x + a.y * b.y + a.z * b.z + a.w * b.w;
}

// ---------------------------------------------------------------------------
// Symmetry-folded DFT matrix init
// ---------------------------------------------------------------------------
__global__ void init_dft_kernel() {
    int i = blockIdx.x * blockDim.x + threadIdx.x;
    if (i < 33 * 34) {
        int r = i / 34, c = i % 34;
        float fc = 0.f, fs = 0.f, ic = 0.f, is = 0.f;
        if (c < 33) {
            float cs = cospif((float)(r * c) / 32.0f);
            float sn = sinpif((float)(r * c) / 32.0f);
            fc = 0.125f * cs;
            fs = -0.125f * sn;
            if (c == 0)       ic = 0.125f;
            else if (c == 32) ic = 0.125f * cospif((float)r);
            else              ic = 0.25f * cs;
            is = -0.25f * sn;
        }
        g_Fc[i] = fc; g_Fs[i] = fs; g_Ic[i] = ic; g_Is[i] = is;
    }
}

// Weight fp32 -> bf16 conversion (both MLP weight matrices)
__global__ void conv_w_kernel(const float* __restrict__ w1,
                              const float* __restrict__ w2) {
    int i = blockIdx.x * blockDim.x + threadIdx.x;
    if (i < 1024 * 256) {
        g_w1bf[i] = __float2bfloat16_rn(w1[i]);
        g_w2bf[i] = __float2bfloat16_rn(w2[i]);
    }
}

// ---------------------------------------------------------------------------
// LayerNorm (fp32 out)
// ---------------------------------------------------------------------------
__global__ void ln_kernel(const float* __restrict__ xin,
                          const float* __restrict__ w,
                          const float* __restrict__ b,
                          float* __restrict__ out, int winmap) {
    __shared__ float red[16];
    int t = blockIdx.x, c = threadIdx.x;
    int rin = winmap ? win2pix(t) : t;
    float v = xin[(size_t)rin * CC + c];
    float s = v, sq = v * v;
    #pragma unroll
    for (int o = 16; o; o >>= 1) {
        s  += __shfl_down_sync(0xffffffffu, s,  o);
        sq += __shfl_down_sync(0xffffffffu, sq, o);
    }
    int warp = c >> 5, lane = c & 31;
    if (lane == 0) { red[warp] = s; red[8 + warp] = sq; }
    __syncthreads();
    if (c == 0) {
        float S = 0.f, Q = 0.f;
        #pragma unroll
        for (int i = 0; i < 8; i++) { S += red[i]; Q += red[8 + i]; }
        red[0] = S * (1.0f / CC);
        red[8] = Q * (1.0f / CC);
    }
    __syncthreads();
    float mean = red[0];
    float var  = red[8] - mean * mean;
    out[(size_t)t * CC + c] = (v - mean) * rsqrtf(var + 1e-5f) * w[c] + b[c];
}

// LayerNorm writing bf16 (LN2 -> fc1 input)
__global__ void ln_bf16_kernel(const float* __restrict__ xin,
                               const float* __restrict__ w,
                               const float* __restrict__ b,
                               __nv_bfloat16* __restrict__ out) {
    __shared__ float red[16];
    int t = blockIdx.x, c = threadIdx.x;
    float v = xin[(size_t)t * CC + c];
    float s = v, sq = v * v;
    #pragma unroll
    for (int o = 16; o; o >>= 1) {
        s  += __shfl_down_sync(0xffffffffu, s,  o);
        sq += __shfl_down_sync(0xffffffffu, sq, o);
    }
    int warp = c >> 5, lane = c & 31;
    if (lane == 0) { red[warp] = s; red[8 + warp] = sq; }
    __syncthreads();
    if (c == 0) {
        float S = 0.f, Q = 0.f;
        #pragma unroll
        for (int i = 0; i < 8; i++) { S += red[i]; Q += red[8 + i]; }
        red[0] = S * (1.0f / CC);
        red[8] = Q * (1.0f / CC);
    }
    __syncthreads();
    float mean = red[0];
    float var  = red[8] - mean * mean;
    out[(size_t)t * CC + c] =
        __float2bfloat16_rn((v - mean) * rsqrtf(var + 1e-5f) * w[c] + b[c]);
}

// ---------------------------------------------------------------------------
// tf32 mma.sync GEMM (qkv + proj)
// ---------------------------------------------------------------------------
#define SMS 36
#define A_STAGE (128 * SMS)
#define B_STAGE (256 * SMS)
#define GEMM_SMEM (3 * (A_STAGE + B_STAGE) * 4)

template<int EPI>
__global__ __launch_bounds__(256, 1)
void gemm_mma(const float* __restrict__ A, const float* __restrict__ W,
              const float* __restrict__ bias, float* __restrict__ C,
              int M, int N, int K, const float* __restrict__ res) {
    extern __shared__ float sm[];
    float* AsBase = sm;
    float* BsBase = sm + 3 * A_STAGE;
    uint32_t sA = smem_u32(AsBase);
    uint32_t sB = smem_u32(BsBase);

    int tid = threadIdx.x;
    int m0 = blockIdx.y * 128, n0 = blockIdx.x * 256;
    int wid = tid >> 5, lane = tid & 31;
    int wm = (wid & 1) * 64, wn = (wid >> 1) * 64;
    int grp = lane >> 2, tg = lane & 3;

    float acc[4][8][4];
    #pragma unroll
    for (int a = 0; a < 4; a++)
        #pragma unroll
        for (int b = 0; b < 8; b++)
            #pragma unroll
            for (int c = 0; c < 4; c++) acc[a][b][c] = 0.f;

    const int NC = K / 32;

    #pragma unroll
    for (int pc = 0; pc < 2; pc++) {
        #pragma unroll
        for (int t = 0; t < 4; t++) {
            int idx = tid + t * 256;
            int row = idx >> 3, q = idx & 7;
            CP_ASYNC16(sA + (uint32_t)(pc * A_STAGE + row * SMS + q * 4) * 4u,
                       A + (size_t)(m0 + row) * K + pc * 32 + q * 4);
        }
        #pragma unroll
        for (int t = 0; t < 8; t++) {
            int idx = tid + t * 256;
            int row = idx >> 3, q = idx & 7;
            CP_ASYNC16(sB + (uint32_t)(pc * B_STAGE + row * SMS + q * 4) * 4u,
                       W + (size_t)(n0 + row) * K + pc * 32 + q * 4);
        }
        CP_COMMIT();
    }

    for (int i = 0; i < NC; i++) {
        if (i + 1 < NC) CP_WAIT1(); else CP_WAIT0();
        __syncthreads();
        if (i + 2 < NC) {
            int st = (i + 2) % 3;
            #pragma unroll
            for (int t = 0; t < 4; t++) {
                int idx = tid + t * 256;
                int row = idx >> 3, q = idx & 7;
                CP_ASYNC16(sA + (uint32_t)(st * A_STAGE + row * SMS + q * 4) * 4u,
                           A + (size_t)(m0 + row) * K + (i + 2) * 32 + q * 4);
            }
            #pragma unroll
            for (int t = 0; t < 8; t++) {
                int idx = tid + t * 256;
                int row = idx >> 3, q = idx & 7;
                CP_ASYNC16(sB + (uint32_t)(st * B_STAGE + row * SMS + q * 4) * 4u,
                           W + (size_t)(n0 + row) * K + (i + 2) * 32 + q * 4);
            }
            CP_COMMIT();
        }

        const float* As = AsBase + (i % 3) * A_STAGE;
        const float* Bs = BsBase + (i % 3) * B_STAGE;
        #pragma unroll
        for (int ks = 0; ks < 4; ks++) {
            uint32_t af[4][4];
            uint32_t bf[8][2];
            #pragma unroll
            for (int mi = 0; mi < 4; mi++) {
                int r = wm + mi * 16 + grp;
                af[mi][0] = __float_as_uint(As[r * SMS + ks * 8 + tg]);
                af[mi][1] = __float_as_uint(As[(r + 8) * SMS + ks * 8 + tg]);
                af[mi][2] = __float_as_uint(As[r * SMS + ks * 8 + tg + 4]);
                af[mi][3] = __float_as_uint(As[(r + 8) * SMS + ks * 8 + tg + 4]);
            }
            #pragma unroll
            for (int ni = 0; ni < 8; ni++) {
                int r = wn + ni * 8 + grp;
                bf[ni][0] = __float_as_uint(Bs[r * SMS + ks * 8 + tg]);
                bf[ni][1] = __float_as_uint(Bs[r * SMS + ks * 8 + tg + 4]);
            }
            #pragma unroll
            for (int mi = 0; mi < 4; mi++)
                #pragma unroll
                for (int ni = 0; ni < 8; ni++)
                    mma16n8k8(acc[mi][ni], af[mi], bf[ni]);
        }
    }

    #pragma unroll
    for (int mi = 0; mi < 4; mi++) {
        #pragma unroll
        for (int half = 0; half < 2; half++) {
            int m = m0 + wm + mi * 16 + grp + half * 8;
            size_t orow = (EPI == 3) ? (size_t)win2pix(m) * N : (size_t)m * N;
            #pragma unroll
            for (int ni = 0; ni < 8; ni++) {
                int n = n0 + wn + ni * 8 + tg * 2;
                float vx = acc[mi][ni][half * 2 + 0] + bias[n];
                float vy = acc[mi][ni][half * 2 + 1] + bias[n + 1];
                if (EPI == 3) {
                    vx += res[orow + n];
                    vy += res[orow + n + 1];
                }
                *(float2*)(C + orow + n) = make_float2(vx, vy);
            }
        }
    }
}

// ---------------------------------------------------------------------------
// bf16 mma.sync GEMM (fc1 / fc2)
// EPI: 1 = GELU -> bf16 store; 2 = +res -> fp32 store
// ---------------------------------------------------------------------------
#define HPAD 72
#define A_STG_H (128 * HPAD)
#define B_STG_H (256 * HPAD)
#define BF_SMEM (3 * (A_STG_H + B_STG_H) * 2)

template<int EPI>
__global__ __launch_bounds__(256, 1)
void gemm_bf16(const __nv_bfloat16* __restrict__ A,
               const __nv_bfloat16* __restrict__ W,
               const float* __restrict__ bias, void* __restrict__ Cv,
               int M, int N, int K, const float* __restrict__ res) {
    extern __shared__ char smc[];
    __nv_bfloat16* AsBase = (__nv_bfloat16*)smc;
    __nv_bfloat16* BsBase = AsBase + 3 * A_STG_H;
    uint32_t sA = smem_u32(AsBase);
    uint32_t sB = smem_u32(BsBase);

    int tid = threadIdx.x;
    int m0 = blockIdx.y * 128, n0 = blockIdx.x * 256;
    int wid = tid >> 5, lane = tid & 31;
    int wm = (wid & 1) * 64, wn = (wid >> 1) * 64;
    int grp = lane >> 2, tg = lane & 3;

    float acc[4][8][4];
    #pragma unroll
    for (int a = 0; a < 4; a++)
        #pragma unroll
        for (int b = 0; b < 8; b++)
            #pragma unroll
            for (int c = 0; c < 4; c++) acc[a][b][c] = 0.f;

    const int NC = K / 64;

    #pragma unroll
    for (int pc = 0; pc < 2; pc++) {
        #pragma unroll
        for (int t = 0; t < 4; t++) {
            int idx = tid + t * 256;
            int row = idx >> 3, q = idx & 7;
            CP_ASYNC16(sA + (uint32_t)(pc * A_STG_H + row * HPAD + q * 8) * 2u,
                       A + (size_t)(m0 + row) * K + pc * 64 + q * 8);
        }
        #pragma unroll
        for (int t = 0; t < 8; t++) {
            int idx = tid + t * 256;
            int row = idx >> 3, q = idx & 7;
            CP_ASYNC16(sB + (uint32_t)(pc * B_STG_H + row * HPAD + q * 8) * 2u,
                       W + (size_t)(n0 + row) * K + pc * 64 + q * 8);
        }
        CP_COMMIT();
    }

    for (int i = 0; i < NC; i++) {
        if (i + 1 < NC) CP_WAIT1(); else CP_WAIT0();
        __syncthreads();
        if (i + 2 < NC) {
            int st = (i + 2) % 3;
            #pragma unroll
            for (int t = 0; t < 4; t++) {
                int idx = tid + t * 256;
                int row = idx >> 3, q = idx & 7;
                CP_ASYNC16(sA + (uint32_t)(st * A_STG_H + row * HPAD + q * 8) * 2u,
                           A + (size_t)(m0 + row) * K + (i + 2) * 64 + q * 8);
            }
            #pragma unroll
            for (int t = 0; t < 8; t++) {
                int idx = tid + t * 256;
                int row = idx >> 3, q = idx & 7;
                CP_ASYNC16(sB + (uint32_t)(st * B_STG_H + row * HPAD + q * 8) * 2u,
                           W + (size_t)(n0 + row) * K + (i + 2) * 64 + q * 8);
            }
            CP_COMMIT();
        }

        const __nv_bfloat16* As = AsBase + (i % 3) * A_STG_H;
        const __nv_bfloat16* Bs = BsBase + (i % 3) * B_STG_H;
        #pragma unroll
        for (int ks = 0; ks < 4; ks++) {          // 4 x k16 = 64
            uint32_t af[4][4];
            uint32_t bf[8][2];
            #pragma unroll
            for (int mi = 0; mi < 4; mi++) {
                int r = wm + mi * 16 + grp;
                af[mi][0] = *(const uint32_t*)(As + r * HPAD + ks * 16 + tg * 2);
                af[mi][1] = *(const uint32_t*)(As + (r + 8) * HPAD + ks * 16 + tg * 2);
                af[mi][2] = *(const uint32_t*)(As + r * HPAD + ks * 16 + tg * 2 + 8);
                af[mi][3] = *(const uint32_t*)(As + (r + 8) * HPAD + ks * 16 + tg * 2 + 8);
            }
            #pragma unroll
            for (int ni = 0; ni < 8; ni++) {
                int r = wn + ni * 8 + grp;
                bf[ni][0] = *(const uint32_t*)(Bs + r * HPAD + ks * 16 + tg * 2);
                bf[ni][1] = *(const uint32_t*)(Bs + r * HPAD + ks * 16 + tg * 2 + 8);
            }
            #pragma unroll
            for (int mi = 0; mi < 4; mi++)
                #pragma unroll
                for (int ni = 0; ni < 8; ni++)
                    mma16n8k16bf(acc[mi][ni], af[mi], bf[ni]);
        }
    }

    #pragma unroll
    for (int mi = 0; mi < 4; mi++) {
        #pragma unroll
        for (int half = 0; half < 2; half++) {
            int m = m0 + wm + mi * 16 + grp + half * 8;
            #pragma unroll
            for (int ni = 0; ni < 8; ni++) {
                int n = n0 + wn + ni * 8 + tg * 2;
                float vx = acc[mi][ni][half * 2 + 0] + bias[n];
                float vy = acc[mi][ni][half * 2 + 1] + bias[n + 1];
                if (EPI == 1) {
                    vx = 0.5f * vx * (1.0f + erff(vx * 0.7071067811865476f));
                    vy = 0.5f * vy * (1.0f + erff(vy * 0.7071067811865476f));
                    __nv_bfloat162* C = (__nv_bfloat162*)Cv;
                    C[((size_t)m * N + n) >> 1] = __floats2bfloat162_rn(vx, vy);
                } else {
                    vx += res[(size_t)m * N + n];
                    vy += res[(size_t)m * N + n + 1];
                    *(float2*)((float*)Cv + (size_t)m * N + n) = make_float2(vx, vy);
                }
            }
        }
    }
}

// ---------------------------------------------------------------------------
// Fused spectral qkv with cos/sin symmetry
// ---------------------------------------------------------------------------
__global__ __launch_bounds__(256)
void spec_qkv_kernel(const float* __restrict__ qkvs,
                     const float* __restrict__ qkvb,
                     float* __restrict__ qkvf) {
    __shared__ float Fc[33 * 34];
    __shared__ float Fs[33 * 34];
    int w = blockIdx.x;
    int tid = threadIdx.x;
    int ch = blockIdx.y * 256 + tid;
    for (int m = tid; m < 33 * 34; m += 256) { Fc[m] = g_Fc[m]; Fs[m] = g_Fs[m]; }

    float e[33], o[32];
    const float* src = qkvs + (size_t)w * NTOK * 768 + ch;
    e[0]  = src[0];
    e[32] = src[(size_t)32 * 768];
    #pragma unroll
    for (int n = 1; n < 32; n++) {
        float a = src[(size_t)n * 768];
        float b = src[(size_t)(64 - n) * 768];
        e[n] = a + b;
        o[n] = a - b;
    }
    __syncthreads();

    float bb = qkvb[ch];
    float* dst = qkvf + (size_t)w * NF * 768 + ch;

    #pragma unroll 1
    for (int f = 0; f < 32; f += 2) {
        const float* R0 = Fc + f * 34;
        const float* R1 = R0 + 34;
        float s0 = 0.f, s0b = 0.f, s1 = 0.f, s1b = 0.f;
        #pragma unroll
        for (int n = 0; n < 32; n += 2) {
            s0  += R0[n] * e[n];     s0b += R0[n + 1] * e[n + 1];
            s1  += R1[n] * e[n];     s1b += R1[n + 1] * e[n + 1];
        }
        s0 += R0[32] * e[32];
        s1 += R1[32] * e[32];
        dst[(size_t)f * 768]       = s0 + s0b + ((f == 0) ? -7.0f * bb : bb);
        dst[(size_t)(f + 1) * 768] = s1 + s1b + bb;
    }
    {
        const float* R0 = Fc + 32 * 34;
        float s0 = 0.f, s0b = 0.f;
        #pragma unroll
        for (int n = 0; n < 32; n += 2) {
            s0 += R0[n] * e[n]; s0b += R0[n + 1] * e[n + 1];
        }
        s0 += R0[32] * e[32];
        dst[(size_t)32 * 768] = s0 + s0b + bb;
    }

    dst[(size_t)33 * 768] = bb;
    dst[(size_t)65 * 768] = bb;

    #pragma unroll 1
    for (int f = 1; f < 31; f += 2) {
        const float* R0 = Fs + f * 34;
        const float* R1 = R0 + 34;
        float s0 = 0.f, s0b = 0.f, s1 = 0.f, s1b = 0.f;
        #pragma unroll
        for (int n = 1; n < 31; n += 2) {
            s0  += R0[n] * o[n];     s0b += R0[n + 1] * o[n + 1];
            s1  += R1[n] * o[n];     s1b += R1[n + 1] * o[n + 1];
        }
        s0 += R0[31] * o[31];
        s1 += R1[31] * o[31];
        dst[(size_t)(33 + f) * 768] = s0 + s0b + bb;
        dst[(size_t)(34 + f) * 768] = s1 + s1b + bb;
    }
    {
        const float* R0 = Fs + 31 * 34;
        float s0 = 0.f, s0b = 0.f;
        #pragma unroll
        for (int n = 1; n < 31; n += 2) {
            s0 += R0[n] * o[n]; s0b += R0[n + 1] * o[n + 1];
        }
        s0 += R0[31] * o[31];
        dst[(size_t)64 * 768] = s0 + s0b + bb;
    }
}

// ---------------------------------------------------------------------------
// Inverse rfft accumulate with symmetry
// ---------------------------------------------------------------------------
__global__ __launch_bounds__(256)
void ifft_acc_kernel(const float* __restrict__ outf,
                     float* __restrict__ acc) {
    __shared__ float Ic[33 * 34];
    __shared__ float Is[33 * 34];
    int w = blockIdx.x;
    int c = threadIdx.x;
    for (int m = c; m < 33 * 34; m += 256) { Ic[m] = g_Ic[m]; Is[m] = g_Is[m]; }

    float fr[NF];
    const float* src = outf + (size_t)w * NF * CC + c;
    #pragma unroll 11
    for (int r = 0; r < NF; r++) fr[r] = src[(size_t)r * CC];
    __syncthreads();

    float* dst = acc + (size_t)w * NTOK * CC + c;
    #pragma unroll 1
    for (int n = 0; n < 32; n += 2) {
        const float* C0 = Ic + n * 34;
        const float* C1 = C0 + 34;
        const float* S0 = Is + n * 34;
        const float* S1 = S0 + 34;
        float a0 = 0.f, a0b = 0.f, a1 = 0.f, a1b = 0.f;
        #pragma unroll
        for (int r = 0; r < 32; r += 2) {
            a0  += C0[r] * fr[r];     a0b += C0[r + 1] * fr[r + 1];
            a1  += C1[r] * fr[r];     a1b += C1[r + 1] * fr[r + 1];
        }
        a0 += C0[32] * fr[32];
        a1 += C1[32] * fr[32];
        float b0 = 0.f, b0b = 0.f, b1 = 0.f, b1b = 0.f;
        #pragma unroll
        for (int r = 1; r < 31; r += 2) {
            b0  += S0[r] * fr[33 + r];     b0b += S0[r + 1] * fr[34 + r];
            b1  += S1[r] * fr[33 + r];     b1b += S1[r + 1] * fr[34 + r];
        }
        b0 += S0[31] * fr[64];
        b1 += S1[31] * fr[64];
        float A0 = a0 + a0b, B0 = b0 + b0b;
        float A1 = a1 + a1b, B1 = b1 + b1b;
        dst[(size_t)n * CC] += A0 + B0;
        if (n >= 1) dst[(size_t)(64 - n) * CC] += A0 - B0;
        dst[(size_t)(n + 1) * CC] += A1 + B1;
        dst[(size_t)(63 - n) * CC] += A1 - B1;
    }
    {
        const float* C0 = Ic + 32 * 34;
        float a0 = 0.f, a0b = 0.f;
        #pragma unroll
        for (int r = 0; r < 32; r += 2) {
            a0 += C0[r] * fr[r]; a0b += C0[r + 1] * fr[r + 1];
        }
        a0 += C0[32] * fr[32];
        dst[(size_t)32 * CC] += a0 + a0b;
    }
}

// ---------------------------------------------------------------------------
// Spatial window attention
// ---------------------------------------------------------------------------
template<int NT, bool BIAS>
__global__ void attn_kernel(const float* __restrict__ qkv,
                            const float* __restrict__ rpb,
                            float* __restrict__ outp) {
    const int NTP = (NT == 64) ? 65 : 67;
    __shared__ float ks[NT][36];
    __shared__ float vs[NT][36];
    __shared__ float ss[NT][NTP];
    __shared__ float rpb_s[BIAS ? 225 : 1];

    int w = blockIdx.x, h = blockIdx.y;
    int row = threadIdx.x;

    float4 qv[8];
    {
        const float4* base = (const float4*)(qkv + ((size_t)w * NT + row) * 768 + h * 32);
        #pragma unroll
        for (int d4 = 0; d4 < 8; d4++) {
            float4 q = base[d4];
            qv[d4] = make_float4(q.x * SCALE, q.y * SCALE, q.z * SCALE, q.w * SCALE);
            *(float4*)&ks[row][d4 * 4] = base[64 + d4];
            *(float4*)&vs[row][d4 * 4] = base[128 + d4];
        }
    }
    if (BIAS) {
        for (int m = row; m < 225; m += NT) rpb_s[m] = rpb[m * HEADS + h];
    }
    __syncthreads();

    int yi = row >> 3, xi = row & 7;
    float mx = -1e30f;
    int j = 0;
    for (; j + 3 < NT; j += 4) {
        const float4* k0 = (const float4*)ks[j + 0];
        const float4* k1 = (const float4*)ks[j + 1];
        const float4* k2 = (const float4*)ks[j + 2];
        const float4* k3 = (const float4*)ks[j + 3];
        float s0 = 0.f, s1 = 0.f, s2 = 0.f, s3 = 0.f;
        #pragma unroll
        for (int d4 = 0; d4 < 8; d4++) {
            float4 q = qv[d4];
            s0 += dot4(q, k0[d4]);
            s1 += dot4(q, k1[d4]);
            s2 += dot4(q, k2[d4]);
            s3 += dot4(q, k3[d4]);
        }
        if (BIAS) {
            int bi = (yi + 7) * 15 + (xi + 7);
            s0 += rpb_s[bi - ((j + 0) >> 3) * 15 - ((j + 0) & 7)];
            s1 += rpb_s[bi - ((j + 1) >> 3) * 15 - ((j + 1) & 7)];
            s2 += rpb_s[bi - ((j + 2) >> 3) * 15 - ((j + 2) & 7)];
            s3 += rpb_s[bi - ((j + 3) >> 3) * 15 - ((j + 3) & 7)];
        }
        ss[row][j + 0] = s0; ss[row][j + 1] = s1;
        ss[row][j + 2] = s2; ss[row][j + 3] = s3;
        mx = fmaxf(mx, fmaxf(fmaxf(s0, s1), fmaxf(s2, s3)));
    }
    for (; j < NT; j++) {
        const float4* k0 = (const float4*)ks[j];
        float s0 = 0.f;
        #pragma unroll
        for (int d4 = 0; d4 < 8; d4++) s0 += dot4(qv[d4], k0[d4]);
        ss[row][j] = s0;
        mx = fmaxf(mx, s0);
    }

    float sum0 = 0.f, sum1 = 0.f;
    for (int jj = 0; jj + 1 < NT; jj += 2) {
        float e0 = __expf(ss[row][jj] - mx);
        float e1 = __expf(ss[row][jj + 1] - mx);
        ss[row][jj] = e0; ss[row][jj + 1] = e1;
        sum0 += e0; sum1 += e1;
    }
    float inv = 1.0f / (sum0 + sum1);

    float4 av[8];
    #pragma unroll
    for (int d4 = 0; d4 < 8; d4++) av[d4] = make_float4(0.f, 0.f, 0.f, 0.f);
    for (int jj = 0; jj + 1 < NT; jj += 2) {
        float p0 = ss[row][jj];
        float p1 = ss[row][jj + 1];
        const float4* v0 = (const float4*)vs[jj];
        const float4* v1 = (const float4*)vs[jj + 1];
        #pragma unroll
        for (int d4 = 0; d4 < 8; d4++) {
            float4 a = av[d4];
            float4 x0 = v0[d4], x1 = v1[d4];
            a.x += p0 * x0.x + p1 * x1.x;
            a.y += p0 * x0.y + p1 * x1.y;
            a.z += p0 * x0.z + p1 * x1.z;
            a.w += p0 * x0.w + p1 * x1.w;
            av[d4] = a;
        }
    }

    float4* ob = (float4*)(outp + ((size_t)w * NT + row) * CC + h * 32);
    #pragma unroll
    for (int d4 = 0; d4 < 8; d4++) {
        float4 a = av[d4];
        ob[d4] = make_float4(a.x * inv, a.y * inv, a.z * inv, a.w * inv);
    }
}

// ---------------------------------------------------------------------------
// Spectral attention: 2 windows per block
// ---------------------------------------------------------------------------
__global__ __launch_bounds__(160)
void attn_spec2_kernel(const float* __restrict__ qkv,
                       float* __restrict__ outp) {
    __shared__ float ks[2][NF][36];
    __shared__ float vs[2][NF][36];
    __shared__ float ss[2][NF][67];

    int w2 = blockIdx.x, h = blockIdx.y;
    int tid = threadIdx.x;
    int sub = tid / NF;
    int row = tid % NF;
    bool act = tid < 2 * NF;
    int w = w2 * 2 + sub;

    float4 qv[8];
    if (act) {
        const float4* base = (const float4*)(qkv + ((size_t)w * NF + row) * 768 + h * 32);
        #pragma unroll
        for (int d4 = 0; d4 < 8; d4++) {
            float4 q = base[d4];
            qv[d4] = make_float4(q.x * SCALE, q.y * SCALE, q.z * SCALE, q.w * SCALE);
            *(float4*)&ks[sub][row][d4 * 4] = base[64 + d4];
            *(float4*)&vs[sub][row][d4 * 4] = base[128 + d4];
        }
    }
    __syncthreads();
    if (!act) return;

    float mx = -1e30f;
    int j = 0;
    for (; j + 3 < NF; j += 4) {
        const float4* k0 = (const float4*)ks[sub][j + 0];
        const float4* k1 = (const float4*)ks[sub][j + 1];
        const float4* k2 = (const float4*)ks[sub][j + 2];
        const float4* k3 = (const float4*)ks[sub][j + 3];
        float s0 = 0.f, s1 = 0.f, s2 = 0.f, s3 = 0.f;
        #pragma unroll
        for (int d4 = 0; d4 < 8; d4++) {
            float4 q = qv[d4];
            s0 += dot4(q, k0[d4]);
            s1 += dot4(q, k1[d4]);
            s2 += dot4(q, k2[d4]);
            s3 += dot4(q, k3[d4]);
        }
        ss[sub][row][j + 0] = s0; ss[sub][row][j + 1] = s1;
        ss[sub][row][j + 2] = s2; ss[sub][row][j + 3] = s3;
        mx = fmaxf(mx, fmaxf(fmaxf(s0, s1), fmaxf(s2, s3)));
    }
    for (; j < NF; j++) {
        const float4* k0 = (const float4*)ks[sub][j];
        float s0 = 0.f;
        #pragma unroll
        for (int d4 = 0; d4 < 8; d4++) s0 += dot4(qv[d4], k0[d4]);
        ss[sub][row][j] = s0;
        mx = fmaxf(mx, s0);
    }

    float sum0 = 0.f, sum1 = 0.f;
    for (int jj = 0; jj + 1 < NF; jj += 2) {
        float e0 = __expf(ss[sub][row][jj] - mx);
        float e1 = __expf(ss[sub][row][jj + 1] - mx);
        ss[sub][row][jj] = e0; ss[sub][row][jj + 1] = e1;
        sum0 += e0; sum1 += e1;
    }
    float inv = 1.0f / (sum0 + sum1);

    float4 av[8];
    #pragma unroll
    for (int d4 = 0; d4 < 8; d4++) av[d4] = make_float4(0.f, 0.f, 0.f, 0.f);
    for (int jj = 0; jj + 1 < NF; jj += 2) {
        float p0 = ss[sub][row][jj];
        float p1 = ss[sub][row][jj + 1];
        const float4* v0 = (const float4*)vs[sub][jj];
        const float4* v1 = (const float4*)vs[sub][jj + 1];
        #pragma unroll
        for (int d4 = 0; d4 < 8; d4++) {
            float4 a = av[d4];
            float4 x0 = v0[d4], x1 = v1[d4];
            a.x += p0 * x0.x + p1 * x1.x;
            a.y += p0 * x0.y + p1 * x1.y;
            a.z += p0 * x0.z + p1 * x1.z;
            a.w += p0 * x0.w + p1 * x1.w;
            av[d4] = a;
        }
    }

    float4* ob = (float4*)(outp + ((size_t)w * NF + row) * CC + h * 32);
    #pragma unroll
    for (int d4 = 0; d4 < 8; d4++) {
        float4 a = av[d4];
        ob[d4] = make_float4(a.x * inv, a.y * inv, a.z * inv, a.w * inv);
    }
}

// ---------------------------------------------------------------------------
// Launch
// ---------------------------------------------------------------------------
extern "C" void kernel_launch(void* const* d_in, const int* in_sizes, int n_in,
                              void* d_out, int out_size) {
    (void)in_sizes; (void)n_in; (void)out_size;
    const float* x     = (const float*)d_in[0];
    const float* n1w   = (const float*)d_in[2];
    const float* n1b   = (const float*)d_in[3];
    const float* qkvw  = (const float*)d_in[4];
    const float* qkvb  = (const float*)d_in[5];
    const float* rpb   = (const float*)d_in[6];
    const float* projw = (const float*)d_in[7];
    const float* projb = (const float*)d_in[8];
    const float* n2w   = (const float*)d_in[9];
    const float* n2b   = (const float*)d_in[10];
    const float* fc1w  = (const float*)d_in[11];
    const float* fc1b  = (const float*)d_in[12];
    const float* fc2w  = (const float*)d_in[13];
    const float* fc2b  = (const float*)d_in[14];
    float* out = (float*)d_out;

    float *xln, *qkvs, *qkvf, *attn, *outf, *x2;
    __nv_bfloat16 *hln, *h1, *w1bf, *w2bf;
    cudaGetSymbolAddress((void**)&xln,  g_xln);
    cudaGetSymbolAddress((void**)&qkvs, g_qkvs);
    cudaGetSymbolAddress((void**)&qkvf, g_qkvf);
    cudaGetSymbolAddress((void**)&attn, g_attn);
    cudaGetSymbolAddress((void**)&outf, g_outf);
    cudaGetSymbolAddress((void**)&x2,   g_x2);
    cudaGetSymbolAddress((void**)&hln,  g_hln);
    cudaGetSymbolAddress((void**)&h1,   g_h1);
    cudaGetSymbolAddress((void**)&w1bf, g_w1bf);
    cudaGetSymbolAddress((void**)&w2bf, g_w2bf);

    cudaFuncSetAttribute(gemm_mma<0>, cudaFuncAttributeMaxDynamicSharedMemorySize, GEMM_SMEM);
    cudaFuncSetAttribute(gemm_mma<3>, cudaFuncAttributeMaxDynamicSharedMemorySize, GEMM_SMEM);
    cudaFuncSetAttribute(gemm_bf16<1>, cudaFuncAttributeMaxDynamicSharedMemorySize, BF_SMEM);
    cudaFuncSetAttribute(gemm_bf16<2>, cudaFuncAttributeMaxDynamicSharedMemorySize, BF_SMEM);

    init_dft_kernel<<<5, 256>>>();
    conv_w_kernel<<<1024, 256>>>(fc1w, fc2w);

    // LN1 (+ window partition)
    ln_kernel<<<TOKS, 256>>>(x, n1w, n1b, xln, 1);

    // spatial qkv (tf32): 131072 x 768
    gemm_mma<0><<<dim3(768 / 256, TOKS / 128), 256, GEMM_SMEM>>>(
        xln, qkvw, qkvb, qkvs, TOKS, 768, 256, nullptr);

    // spectral qkv via DFT of spatial qkv
    spec_qkv_kernel<<<dim3(NWIN, 3), 256>>>(qkvs, qkvb, qkvf);

    // attention
    attn_kernel<NTOK, true><<<dim3(NWIN, HEADS), NTOK>>>(qkvs, rpb, attn);
    attn_spec2_kernel<<<dim3(NWIN / 2, HEADS), 160>>>(qkvf, outf);

    // irfft accumulate
    ifft_acc_kernel<<<NWIN, 256>>>(outf, attn);

    // proj + window reverse + shortcut (tf32) -> x2
    gemm_mma<3><<<dim3(256 / 256, TOKS / 128), 256, GEMM_SMEM>>>(
        attn, projw, projb, x2, TOKS, 256, 256, x);

    // LN2 -> bf16
    ln_bf16_kernel<<<TOKS, 256>>>(x2, n2w, n2b, hln);

    // fc1 + GELU (bf16) -> h1 (bf16)
    gemm_bf16<1><<<dim3(1024 / 256, TOKS / 128), 256, BF_SMEM>>>(
        hln, w1bf, fc1b, h1, TOKS, 1024, 256, nullptr);

    // fc2 + residual (bf16 inputs, fp32 out) -> out
    gemm_bf16<2><<<dim3(256 / 256, TOKS / 128), 256, BF_SMEM>>>(
        h1, w2bf, fc2b, out, TOKS, 256, 1024, x2);
}

// round 10
// speedup vs baseline: 3.9669x; 1.1269x over previous
#include <cuda_runtime.h>
#include <cuda_bf16.h>
#include <math.h>
#include <stdint.h>

// ---------------------------------------------------------------------------
// Problem constants
// ---------------------------------------------------------------------------
#define CC      256
#define WS      8
#define NTOK    64
#define NF      66
#define HEADS   8
#define HD      32
#define NWIN    2048
#define TOKS    131072
#define SCALE   0.17677669529663687f

// ---------------------------------------------------------------------------
// Scratch
// ---------------------------------------------------------------------------
__device__ __nv_bfloat16 g_xlnbf[ (size_t)TOKS * CC ];          // LN1 out (bf16)
__device__ float g_qkvs[ (size_t)NWIN * NTOK * 3 * CC ];        // spatial qkv (fp32)
__device__ __nv_bfloat16 g_qkvf[ (size_t)NWIN * NF * 3 * CC ];  // spectral qkv (bf16)
__device__ float g_attn[ (size_t)NWIN * NTOK * CC ];            // spatial attn out (fp32)
__device__ __nv_bfloat16 g_attnbf[ (size_t)NWIN * NTOK * CC ];  // attn + xr (bf16)
__device__ float g_outf[ (size_t)NWIN * NF   * CC ];            // spectral attn out
__device__ float g_x2  [ (size_t)TOKS * CC ];
__device__ __nv_bfloat16 g_hln[ (size_t)TOKS * CC ];            // LN2 out (bf16)
__device__ __nv_bfloat16 g_h1 [ (size_t)TOKS * 4 * CC ];        // fc1+gelu out (bf16)
__device__ __nv_bfloat16 g_w1bf[ 1024 * 256 ];
__device__ __nv_bfloat16 g_w2bf[ 256 * 1024 ];
__device__ __nv_bfloat16 g_wqbf[ 768 * 256 ];
__device__ __nv_bfloat16 g_wpbf[ 256 * 256 ];
// Half-size symmetry-folded DFT matrices (33 rows x 34-padded cols)
__device__ float g_Fc[ 33 * 34 ];
__device__ float g_Fs[ 33 * 34 ];
__device__ float g_Ic[ 33 * 34 ];
__device__ float g_Is[ 33 * 34 ];

// ---------------------------------------------------------------------------
// Helpers
// ---------------------------------------------------------------------------
__device__ __forceinline__ uint32_t smem_u32(const void* p) {
    uint32_t a;
    asm("{ .reg .u64 t; cvta.to.shared.u64 t, %1; cvt.u32.u64 %0, t; }"
        : "=r"(a) : "l"(p));
    return a;
}

#define CP_ASYNC16(dst_u32, src_ptr) \
    asm volatile("cp.async.cg.shared.global [%0], [%1], 16;" \
        :: "r"(dst_u32), "l"(src_ptr))
#define CP_COMMIT() asm volatile("cp.async.commit_group;")
#define CP_WAIT1()  asm volatile("cp.async.wait_group 1;")
#define CP_WAIT0()  asm volatile("cp.async.wait_group 0;")

__device__ __forceinline__ void mma16n8k16bf(float* c, const uint32_t* a,
                                             const uint32_t* b) {
    asm volatile(
        "mma.sync.aligned.m16n8k16.row.col.f32.bf16.bf16.f32 "
        "{%0,%1,%2,%3}, {%4,%5,%6,%7}, {%8,%9}, {%0,%1,%2,%3};"
        : "+f"(c[0]), "+f"(c[1]), "+f"(c[2]), "+f"(c[3])
        : "r"(a[0]), "r"(a[1]), "r"(a[2]), "r"(a[3]), "r"(b[0]), "r"(b[1]));
}

__device__ __forceinline__ int win2pix(int t) {
    int b   = t >> 16;
    int rem = t & 65535;
    int wl  = rem >> 6;
    int n   = rem & 63;
    int wh  = wl >> 5, ww = wl & 31;
    int i   = n >> 3,  j  = n & 7;
    return (b * 256 + wh * 8 + i) * 256 + (ww * 8 + j);
}

__device__ __forceinline__ float dot4(float4 a, float4 b) {
    return a.x * b.x + a.y * b.y + a.z * b.z + a.w * b.w;
}

// Convert 8 packed bf16 (uint4) to 8 floats
__device__ __forceinline__ void bf8_to_f8(uint4 r, float* o) {
    const __nv_bfloat162* p = (const __nv_bfloat162*)&r;
    #pragma unroll
    for (int i = 0; i < 4; i++) {
        float2 f = __bfloat1622float2(p[i]);
        o[2 * i] = f.x; o[2 * i + 1] = f.y;
    }
}

// ---------------------------------------------------------------------------
// Symmetry-folded DFT matrix init
// ---------------------------------------------------------------------------
__global__ void init_dft_kernel() {
    int i = blockIdx.x * blockDim.x + threadIdx.x;
    if (i < 33 * 34) {
        int r = i / 34, c = i % 34;
        float fc = 0.f, fs = 0.f, ic = 0.f, is = 0.f;
        if (c < 33) {
            float cs = cospif((float)(r * c) / 32.0f);
            float sn = sinpif((float)(r * c) / 32.0f);
            fc = 0.125f * cs;
            fs = -0.125f * sn;
            if (c == 0)       ic = 0.125f;
            else if (c == 32) ic = 0.125f * cospif((float)r);
            else              ic = 0.25f * cs;
            is = -0.25f * sn;
        }
        g_Fc[i] = fc; g_Fs[i] = fs; g_Ic[i] = ic; g_Is[i] = is;
    }
}

// Weight fp32 -> bf16 conversion (all four GEMM weight matrices)
__global__ void conv_w_kernel(const float* __restrict__ w1,
                              const float* __restrict__ w2,
                              const float* __restrict__ wq,
                              const float* __restrict__ wp) {
    int i = blockIdx.x * blockDim.x + threadIdx.x;
    if (i < 1024 * 256) {
        g_w1bf[i] = __float2bfloat16_rn(w1[i]);
        g_w2bf[i] = __float2bfloat16_rn(w2[i]);
    }
    if (i < 768 * 256)  g_wqbf[i] = __float2bfloat16_rn(wq[i]);
    if (i < 256 * 256)  g_wpbf[i] = __float2bfloat16_rn(wp[i]);
}

// ---------------------------------------------------------------------------
// LayerNorm writing bf16; winmap=1: pixel->window order (LN1), 0: plain (LN2)
// ---------------------------------------------------------------------------
__global__ void ln_bf16_kernel(const float* __restrict__ xin,
                               const float* __restrict__ w,
                               const float* __restrict__ b,
                               __nv_bfloat16* __restrict__ out, int winmap) {
    __shared__ float red[16];
    int t = blockIdx.x, c = threadIdx.x;
    int rin = winmap ? win2pix(t) : t;
    float v = xin[(size_t)rin * CC + c];
    float s = v, sq = v * v;
    #pragma unroll
    for (int o = 16; o; o >>= 1) {
        s  += __shfl_down_sync(0xffffffffu, s,  o);
        sq += __shfl_down_sync(0xffffffffu, sq, o);
    }
    int warp = c >> 5, lane = c & 31;
    if (lane == 0) { red[warp] = s; red[8 + warp] = sq; }
    __syncthreads();
    if (c == 0) {
        float S = 0.f, Q = 0.f;
        #pragma unroll
        for (int i = 0; i < 8; i++) { S += red[i]; Q += red[8 + i]; }
        red[0] = S * (1.0f / CC);
        red[8] = Q * (1.0f / CC);
    }
    __syncthreads();
    float mean = red[0];
    float var  = red[8] - mean * mean;
    out[(size_t)t * CC + c] =
        __float2bfloat16_rn((v - mean) * rsqrtf(var + 1e-5f) * w[c] + b[c]);
}

// ---------------------------------------------------------------------------
// bf16 mma.sync GEMM: C = A @ W^T + bias (+epilogue)
// 128x256 CTA tile, BK=64 bf16, 8 warps (2x4), warp tile 64x64, rows pad 72.
// EPI: 0 plain fp32; 1 GELU -> bf16; 2 +res fp32; 3 window-reverse +res fp32
// ---------------------------------------------------------------------------
#define HPAD 72
#define A_STG_H (128 * HPAD)
#define B_STG_H (256 * HPAD)
#define BF_SMEM (3 * (A_STG_H + B_STG_H) * 2)

template<int EPI>
__global__ __launch_bounds__(256, 1)
void gemm_bf16(const __nv_bfloat16* __restrict__ A,
               const __nv_bfloat16* __restrict__ W,
               const float* __restrict__ bias, void* __restrict__ Cv,
               int M, int N, int K, const float* __restrict__ res) {
    extern __shared__ char smc[];
    __nv_bfloat16* AsBase = (__nv_bfloat16*)smc;
    __nv_bfloat16* BsBase = AsBase + 3 * A_STG_H;
    uint32_t sA = smem_u32(AsBase);
    uint32_t sB = smem_u32(BsBase);

    int tid = threadIdx.x;
    int m0 = blockIdx.y * 128, n0 = blockIdx.x * 256;
    int wid = tid >> 5, lane = tid & 31;
    int wm = (wid & 1) * 64, wn = (wid >> 1) * 64;
    int grp = lane >> 2, tg = lane & 3;

    float acc[4][8][4];
    #pragma unroll
    for (int a = 0; a < 4; a++)
        #pragma unroll
        for (int b = 0; b < 8; b++)
            #pragma unroll
            for (int c = 0; c < 4; c++) acc[a][b][c] = 0.f;

    const int NC = K / 64;

    #pragma unroll
    for (int pc = 0; pc < 2; pc++) {
        #pragma unroll
        for (int t = 0; t < 4; t++) {
            int idx = tid + t * 256;
            int row = idx >> 3, q = idx & 7;
            CP_ASYNC16(sA + (uint32_t)(pc * A_STG_H + row * HPAD + q * 8) * 2u,
                       A + (size_t)(m0 + row) * K + pc * 64 + q * 8);
        }
        #pragma unroll
        for (int t = 0; t < 8; t++) {
            int idx = tid + t * 256;
            int row = idx >> 3, q = idx & 7;
            CP_ASYNC16(sB + (uint32_t)(pc * B_STG_H + row * HPAD + q * 8) * 2u,
                       W + (size_t)(n0 + row) * K + pc * 64 + q * 8);
        }
        CP_COMMIT();
    }

    for (int i = 0; i < NC; i++) {
        if (i + 1 < NC) CP_WAIT1(); else CP_WAIT0();
        __syncthreads();
        if (i + 2 < NC) {
            int st = (i + 2) % 3;
            #pragma unroll
            for (int t = 0; t < 4; t++) {
                int idx = tid + t * 256;
                int row = idx >> 3, q = idx & 7;
                CP_ASYNC16(sA + (uint32_t)(st * A_STG_H + row * HPAD + q * 8) * 2u,
                           A + (size_t)(m0 + row) * K + (i + 2) * 64 + q * 8);
            }
            #pragma unroll
            for (int t = 0; t < 8; t++) {
                int idx = tid + t * 256;
                int row = idx >> 3, q = idx & 7;
                CP_ASYNC16(sB + (uint32_t)(st * B_STG_H + row * HPAD + q * 8) * 2u,
                           W + (size_t)(n0 + row) * K + (i + 2) * 64 + q * 8);
            }
            CP_COMMIT();
        }

        const __nv_bfloat16* As = AsBase + (i % 3) * A_STG_H;
        const __nv_bfloat16* Bs = BsBase + (i % 3) * B_STG_H;
        #pragma unroll
        for (int ks = 0; ks < 4; ks++) {
            uint32_t af[4][4];
            uint32_t bf[8][2];
            #pragma unroll
            for (int mi = 0; mi < 4; mi++) {
                int r = wm + mi * 16 + grp;
                af[mi][0] = *(const uint32_t*)(As + r * HPAD + ks * 16 + tg * 2);
                af[mi][1] = *(const uint32_t*)(As + (r + 8) * HPAD + ks * 16 + tg * 2);
                af[mi][2] = *(const uint32_t*)(As + r * HPAD + ks * 16 + tg * 2 + 8);
                af[mi][3] = *(const uint32_t*)(As + (r + 8) * HPAD + ks * 16 + tg * 2 + 8);
            }
            #pragma unroll
            for (int ni = 0; ni < 8; ni++) {
                int r = wn + ni * 8 + grp;
                bf[ni][0] = *(const uint32_t*)(Bs + r * HPAD + ks * 16 + tg * 2);
                bf[ni][1] = *(const uint32_t*)(Bs + r * HPAD + ks * 16 + tg * 2 + 8);
            }
            #pragma unroll
            for (int mi = 0; mi < 4; mi++)
                #pragma unroll
                for (int ni = 0; ni < 8; ni++)
                    mma16n8k16bf(acc[mi][ni], af[mi], bf[ni]);
        }
    }

    #pragma unroll
    for (int mi = 0; mi < 4; mi++) {
        #pragma unroll
        for (int half = 0; half < 2; half++) {
            int m = m0 + wm + mi * 16 + grp + half * 8;
            size_t orow = (EPI == 3) ? (size_t)win2pix(m) * N : (size_t)m * N;
            #pragma unroll
            for (int ni = 0; ni < 8; ni++) {
                int n = n0 + wn + ni * 8 + tg * 2;
                float vx = acc[mi][ni][half * 2 + 0] + bias[n];
                float vy = acc[mi][ni][half * 2 + 1] + bias[n + 1];
                if (EPI == 1) {
                    vx = 0.5f * vx * (1.0f + erff(vx * 0.7071067811865476f));
                    vy = 0.5f * vy * (1.0f + erff(vy * 0.7071067811865476f));
                    __nv_bfloat162* C = (__nv_bfloat162*)Cv;
                    C[(orow + n) >> 1] = __floats2bfloat162_rn(vx, vy);
                } else {
                    if (EPI == 2 || EPI == 3) {
                        vx += res[orow + n];
                        vy += res[orow + n + 1];
                    }
                    *(float2*)((float*)Cv + orow + n) = make_float2(vx, vy);
                }
            }
        }
    }
}

// ---------------------------------------------------------------------------
// Fused spectral qkv with cos/sin symmetry -> bf16 output
// ---------------------------------------------------------------------------
__global__ __launch_bounds__(256)
void spec_qkv_kernel(const float* __restrict__ qkvs,
                     const float* __restrict__ qkvb,
                     __nv_bfloat16* __restrict__ qkvf) {
    __shared__ float Fc[33 * 34];
    __shared__ float Fs[33 * 34];
    int w = blockIdx.x;
    int tid = threadIdx.x;
    int ch = blockIdx.y * 256 + tid;
    for (int m = tid; m < 33 * 34; m += 256) { Fc[m] = g_Fc[m]; Fs[m] = g_Fs[m]; }

    float e[33], o[32];
    const float* src = qkvs + (size_t)w * NTOK * 768 + ch;
    e[0]  = src[0];
    e[32] = src[(size_t)32 * 768];
    #pragma unroll
    for (int n = 1; n < 32; n++) {
        float a = src[(size_t)n * 768];
        float b = src[(size_t)(64 - n) * 768];
        e[n] = a + b;
        o[n] = a - b;
    }
    __syncthreads();

    float bb = qkvb[ch];
    __nv_bfloat16* dst = qkvf + (size_t)w * NF * 768 + ch;

    #pragma unroll 1
    for (int f = 0; f < 32; f += 2) {
        const float* R0 = Fc + f * 34;
        const float* R1 = R0 + 34;
        float s0 = 0.f, s0b = 0.f, s1 = 0.f, s1b = 0.f;
        #pragma unroll
        for (int n = 0; n < 32; n += 2) {
            s0  += R0[n] * e[n];     s0b += R0[n + 1] * e[n + 1];
            s1  += R1[n] * e[n];     s1b += R1[n + 1] * e[n + 1];
        }
        s0 += R0[32] * e[32];
        s1 += R1[32] * e[32];
        dst[(size_t)f * 768]       = __float2bfloat16_rn(s0 + s0b + ((f == 0) ? -7.0f * bb : bb));
        dst[(size_t)(f + 1) * 768] = __float2bfloat16_rn(s1 + s1b + bb);
    }
    {
        const float* R0 = Fc + 32 * 34;
        float s0 = 0.f, s0b = 0.f;
        #pragma unroll
        for (int n = 0; n < 32; n += 2) {
            s0 += R0[n] * e[n]; s0b += R0[n + 1] * e[n + 1];
        }
        s0 += R0[32] * e[32];
        dst[(size_t)32 * 768] = __float2bfloat16_rn(s0 + s0b + bb);
    }

    dst[(size_t)33 * 768] = __float2bfloat16_rn(bb);
    dst[(size_t)65 * 768] = __float2bfloat16_rn(bb);

    #pragma unroll 1
    for (int f = 1; f < 31; f += 2) {
        const float* R0 = Fs + f * 34;
        const float* R1 = R0 + 34;
        float s0 = 0.f, s0b = 0.f, s1 = 0.f, s1b = 0.f;
        #pragma unroll
        for (int n = 1; n < 31; n += 2) {
            s0  += R0[n] * o[n];     s0b += R0[n + 1] * o[n + 1];
            s1  += R1[n] * o[n];     s1b += R1[n + 1] * o[n + 1];
        }
        s0 += R0[31] * o[31];
        s1 += R1[31] * o[31];
        dst[(size_t)(33 + f) * 768] = __float2bfloat16_rn(s0 + s0b + bb);
        dst[(size_t)(34 + f) * 768] = __float2bfloat16_rn(s1 + s1b + bb);
    }
    {
        const float* R0 = Fs + 31 * 34;
        float s0 = 0.f, s0b = 0.f;
        #pragma unroll
        for (int n = 1; n < 31; n += 2) {
            s0 += R0[n] * o[n]; s0b += R0[n + 1] * o[n + 1];
        }
        s0 += R0[31] * o[31];
        dst[(size_t)64 * 768] = __float2bfloat16_rn(s0 + s0b + bb);
    }
}

// ---------------------------------------------------------------------------
// Inverse rfft: attnbf = bf16(attn + irfft(outf)); every (n,c) written once.
// ---------------------------------------------------------------------------
__global__ __launch_bounds__(256)
void ifft_acc_kernel(const float* __restrict__ outf,
                     const float* __restrict__ attn,
                     __nv_bfloat16* __restrict__ attnbf) {
    __shared__ float Ic[33 * 34];
    __shared__ float Is[33 * 34];
    int w = blockIdx.x;
    int c = threadIdx.x;
    for (int m = c; m < 33 * 34; m += 256) { Ic[m] = g_Ic[m]; Is[m] = g_Is[m]; }

    float fr[NF];
    const float* src = outf + (size_t)w * NF * CC + c;
    #pragma unroll 11
    for (int r = 0; r < NF; r++) fr[r] = src[(size_t)r * CC];
    __syncthreads();

    const float* ain = attn + (size_t)w * NTOK * CC + c;
    __nv_bfloat16* dst = attnbf + (size_t)w * NTOK * CC + c;
    #pragma unroll 1
    for (int n = 0; n < 32; n += 2) {
        const float* C0 = Ic + n * 34;
        const float* C1 = C0 + 34;
        const float* S0 = Is + n * 34;
        const float* S1 = S0 + 34;
        float a0 = 0.f, a0b = 0.f, a1 = 0.f, a1b = 0.f;
        #pragma unroll
        for (int r = 0; r < 32; r += 2) {
            a0  += C0[r] * fr[r];     a0b += C0[r + 1] * fr[r + 1];
            a1  += C1[r] * fr[r];     a1b += C1[r + 1] * fr[r + 1];
        }
        a0 += C0[32] * fr[32];
        a1 += C1[32] * fr[32];
        float b0 = 0.f, b0b = 0.f, b1 = 0.f, b1b = 0.f;
        #pragma unroll
        for (int r = 1; r < 31; r += 2) {
            b0  += S0[r] * fr[33 + r];     b0b += S0[r + 1] * fr[34 + r];
            b1  += S1[r] * fr[33 + r];     b1b += S1[r + 1] * fr[34 + r];
        }
        b0 += S0[31] * fr[64];
        b1 += S1[31] * fr[64];
        float A0 = a0 + a0b, B0 = b0 + b0b;
        float A1 = a1 + a1b, B1 = b1 + b1b;
        dst[(size_t)n * CC] = __float2bfloat16_rn(ain[(size_t)n * CC] + A0 + B0);
        if (n >= 1)
            dst[(size_t)(64 - n) * CC] =
                __float2bfloat16_rn(ain[(size_t)(64 - n) * CC] + A0 - B0);
        dst[(size_t)(n + 1) * CC] =
            __float2bfloat16_rn(ain[(size_t)(n + 1) * CC] + A1 + B1);
        dst[(size_t)(63 - n) * CC] =
            __float2bfloat16_rn(ain[(size_t)(63 - n) * CC] + A1 - B1);
    }
    {
        const float* C0 = Ic + 32 * 34;
        float a0 = 0.f, a0b = 0.f;
        #pragma unroll
        for (int r = 0; r < 32; r += 2) {
            a0 += C0[r] * fr[r]; a0b += C0[r + 1] * fr[r + 1];
        }
        a0 += C0[32] * fr[32];
        dst[(size_t)32 * CC] = __float2bfloat16_rn(ain[(size_t)32 * CC] + a0 + a0b);
    }
}

// ---------------------------------------------------------------------------
// Spatial window attention (fp32 qkv input, unchanged math)
// ---------------------------------------------------------------------------
template<int NT, bool BIAS>
__global__ void attn_kernel(const float* __restrict__ qkv,
                            const float* __restrict__ rpb,
                            float* __restrict__ outp) {
    const int NTP = (NT == 64) ? 65 : 67;
    __shared__ float ks[NT][36];
    __shared__ float vs[NT][36];
    __shared__ float ss[NT][NTP];
    __shared__ float rpb_s[BIAS ? 225 : 1];

    int w = blockIdx.x, h = blockIdx.y;
    int row = threadIdx.x;

    float4 qv[8];
    {
        const float4* base = (const float4*)(qkv + ((size_t)w * NT + row) * 768 + h * 32);
        #pragma unroll
        for (int d4 = 0; d4 < 8; d4++) {
            float4 q = base[d4];
            qv[d4] = make_float4(q.x * SCALE, q.y * SCALE, q.z * SCALE, q.w * SCALE);
            *(float4*)&ks[row][d4 * 4] = base[64 + d4];
            *(float4*)&vs[row][d4 * 4] = base[128 + d4];
        }
    }
    if (BIAS) {
        for (int m = row; m < 225; m += NT) rpb_s[m] = rpb[m * HEADS + h];
    }
    __syncthreads();

    int yi = row >> 3, xi = row & 7;
    float mx = -1e30f;
    int j = 0;
    for (; j + 3 < NT; j += 4) {
        const float4* k0 = (const float4*)ks[j + 0];
        const float4* k1 = (const float4*)ks[j + 1];
        const float4* k2 = (const float4*)ks[j + 2];
        const float4* k3 = (const float4*)ks[j + 3];
        float s0 = 0.f, s1 = 0.f, s2 = 0.f, s3 = 0.f;
        #pragma unroll
        for (int d4 = 0; d4 < 8; d4++) {
            float4 q = qv[d4];
            s0 += dot4(q, k0[d4]);
            s1 += dot4(q, k1[d4]);
            s2 += dot4(q, k2[d4]);
            s3 += dot4(q, k3[d4]);
        }
        if (BIAS) {
            int bi = (yi + 7) * 15 + (xi + 7);
            s0 += rpb_s[bi - ((j + 0) >> 3) * 15 - ((j + 0) & 7)];
            s1 += rpb_s[bi - ((j + 1) >> 3) * 15 - ((j + 1) & 7)];
            s2 += rpb_s[bi - ((j + 2) >> 3) * 15 - ((j + 2) & 7)];
            s3 += rpb_s[bi - ((j + 3) >> 3) * 15 - ((j + 3) & 7)];
        }
        ss[row][j + 0] = s0; ss[row][j + 1] = s1;
        ss[row][j + 2] = s2; ss[row][j + 3] = s3;
        mx = fmaxf(mx, fmaxf(fmaxf(s0, s1), fmaxf(s2, s3)));
    }
    for (; j < NT; j++) {
        const float4* k0 = (const float4*)ks[j];
        float s0 = 0.f;
        #pragma unroll
        for (int d4 = 0; d4 < 8; d4++) s0 += dot4(qv[d4], k0[d4]);
        ss[row][j] = s0;
        mx = fmaxf(mx, s0);
    }

    float sum0 = 0.f, sum1 = 0.f;
    for (int jj = 0; jj + 1 < NT; jj += 2) {
        float e0 = __expf(ss[row][jj] - mx);
        float e1 = __expf(ss[row][jj + 1] - mx);
        ss[row][jj] = e0; ss[row][jj + 1] = e1;
        sum0 += e0; sum1 += e1;
    }
    float inv = 1.0f / (sum0 + sum1);

    float4 av[8];
    #pragma unroll
    for (int d4 = 0; d4 < 8; d4++) av[d4] = make_float4(0.f, 0.f, 0.f, 0.f);
    for (int jj = 0; jj + 1 < NT; jj += 2) {
        float p0 = ss[row][jj];
        float p1 = ss[row][jj + 1];
        const float4* v0 = (const float4*)vs[jj];
        const float4* v1 = (const float4*)vs[jj + 1];
        #pragma unroll
        for (int d4 = 0; d4 < 8; d4++) {
            float4 a = av[d4];
            float4 x0 = v0[d4], x1 = v1[d4];
            a.x += p0 * x0.x + p1 * x1.x;
            a.y += p0 * x0.y + p1 * x1.y;
            a.z += p0 * x0.z + p1 * x1.z;
            a.w += p0 * x0.w + p1 * x1.w;
            av[d4] = a;
        }
    }

    float4* ob = (float4*)(outp + ((size_t)w * NT + row) * CC + h * 32);
    #pragma unroll
    for (int d4 = 0; d4 < 8; d4++) {
        float4 a = av[d4];
        ob[d4] = make_float4(a.x * inv, a.y * inv, a.z * inv, a.w * inv);
    }
}

// ---------------------------------------------------------------------------
// Spectral attention: 2 windows per block, bf16 qkv input.
// ---------------------------------------------------------------------------
__global__ __launch_bounds__(160)
void attn_spec2_kernel(const __nv_bfloat16* __restrict__ qkv,
                       float* __restrict__ outp) {
    __shared__ float ks[2][NF][36];
    __shared__ float vs[2][NF][36];
    __shared__ float ss[2][NF][67];

    int w2 = blockIdx.x, h = blockIdx.y;
    int tid = threadIdx.x;
    int sub = tid / NF;
    int row = tid % NF;
    bool act = tid < 2 * NF;
    int w = w2 * 2 + sub;

    float4 qv[8];
    if (act) {
        const uint4* base = (const uint4*)(qkv + ((size_t)w * NF + row) * 768 + h * 32);
        // q: uint4 0..3 ; k: +256 bf16 = uint4 32..35 ; v: 64..67
        #pragma unroll
        for (int i = 0; i < 4; i++) {
            float qf[8];
            bf8_to_f8(base[i], qf);
            qv[2 * i]     = make_float4(qf[0] * SCALE, qf[1] * SCALE, qf[2] * SCALE, qf[3] * SCALE);
            qv[2 * i + 1] = make_float4(qf[4] * SCALE, qf[5] * SCALE, qf[6] * SCALE, qf[7] * SCALE);
            bf8_to_f8(base[32 + i], &ks[sub][row][i * 8]);
            bf8_to_f8(base[64 + i], &vs[sub][row][i * 8]);
        }
    }
    __syncthreads();
    if (!act) return;

    float mx = -1e30f;
    int j = 0;
    for (; j + 3 < NF; j += 4) {
        const float4* k0 = (const float4*)ks[sub][j + 0];
        const float4* k1 = (const float4*)ks[sub][j + 1];
        const float4* k2 = (const float4*)ks[sub][j + 2];
        const float4* k3 = (const float4*)ks[sub][j + 3];
        float s0 = 0.f, s1 = 0.f, s2 = 0.f, s3 = 0.f;
        #pragma unroll
        for (int d4 = 0; d4 < 8; d4++) {
            float4 q = qv[d4];
            s0 += dot4(q, k0[d4]);
            s1 += dot4(q, k1[d4]);
            s2 += dot4(q, k2[d4]);
            s3 += dot4(q, k3[d4]);
        }
        ss[sub][row][j + 0] = s0; ss[sub][row][j + 1] = s1;
        ss[sub][row][j + 2] = s2; ss[sub][row][j + 3] = s3;
        mx = fmaxf(mx, fmaxf(fmaxf(s0, s1), fmaxf(s2, s3)));
    }
    for (; j < NF; j++) {
        const float4* k0 = (const float4*)ks[sub][j];
        float s0 = 0.f;
        #pragma unroll
        for (int d4 = 0; d4 < 8; d4++) s0 += dot4(qv[d4], k0[d4]);
        ss[sub][row][j] = s0;
        mx = fmaxf(mx, s0);
    }

    float sum0 = 0.f, sum1 = 0.f;
    for (int jj = 0; jj + 1 < NF; jj += 2) {
        float e0 = __expf(ss[sub][row][jj] - mx);
        float e1 = __expf(ss[sub][row][jj + 1] - mx);
        ss[sub][row][jj] = e0; ss[sub][row][jj + 1] = e1;
        sum0 += e0; sum1 += e1;
    }
    float inv = 1.0f / (sum0 + sum1);

    float4 av[8];
    #pragma unroll
    for (int d4 = 0; d4 < 8; d4++) av[d4] = make_float4(0.f, 0.f, 0.f, 0.f);
    for (int jj = 0; jj + 1 < NF; jj += 2) {
        float p0 = ss[sub][row][jj];
        float p1 = ss[sub][row][jj + 1];
        const float4* v0 = (const float4*)vs[sub][jj];
        const float4* v1 = (const float4*)vs[sub][jj + 1];
        #pragma unroll
        for (int d4 = 0; d4 < 8; d4++) {
            float4 a = av[d4];
            float4 x0 = v0[d4], x1 = v1[d4];
            a.x += p0 * x0.x + p1 * x1.x;
            a.y += p0 * x0.y + p1 * x1.y;
            a.z += p0 * x0.z + p1 * x1.z;
            a.w += p0 * x0.w + p1 * x1.w;
            av[d4] = a;
        }
    }

    float4* ob = (float4*)(outp + ((size_t)w * NF + row) * CC + h * 32);
    #pragma unroll
    for (int d4 = 0; d4 < 8; d4++) {
        float4 a = av[d4];
        ob[d4] = make_float4(a.x * inv, a.y * inv, a.z * inv, a.w * inv);
    }
}

// ---------------------------------------------------------------------------
// Launch
// ---------------------------------------------------------------------------
extern "C" void kernel_launch(void* const* d_in, const int* in_sizes, int n_in,
                              void* d_out, int out_size) {
    (void)in_sizes; (void)n_in; (void)out_size;
    const float* x     = (const float*)d_in[0];
    const float* n1w   = (const float*)d_in[2];
    const float* n1b   = (const float*)d_in[3];
    const float* qkvw  = (const float*)d_in[4];
    const float* qkvb  = (const float*)d_in[5];
    const float* rpb   = (const float*)d_in[6];
    const float* projw = (const float*)d_in[7];
    const float* projb = (const float*)d_in[8];
    const float* n2w   = (const float*)d_in[9];
    const float* n2b   = (const float*)d_in[10];
    const float* fc1w  = (const float*)d_in[11];
    const float* fc1b  = (const float*)d_in[12];
    const float* fc2w  = (const float*)d_in[13];
    const float* fc2b  = (const float*)d_in[14];
    float* out = (float*)d_out;

    float *qkvs, *attn, *outf, *x2;
    __nv_bfloat16 *xlnbf, *qkvf, *attnbf, *hln, *h1, *w1bf, *w2bf, *wqbf, *wpbf;
    cudaGetSymbolAddress((void**)&xlnbf,  g_xlnbf);
    cudaGetSymbolAddress((void**)&qkvs,   g_qkvs);
    cudaGetSymbolAddress((void**)&qkvf,   g_qkvf);
    cudaGetSymbolAddress((void**)&attn,   g_attn);
    cudaGetSymbolAddress((void**)&attnbf, g_attnbf);
    cudaGetSymbolAddress((void**)&outf,   g_outf);
    cudaGetSymbolAddress((void**)&x2,     g_x2);
    cudaGetSymbolAddress((void**)&hln,    g_hln);
    cudaGetSymbolAddress((void**)&h1,     g_h1);
    cudaGetSymbolAddress((void**)&w1bf,   g_w1bf);
    cudaGetSymbolAddress((void**)&w2bf,   g_w2bf);
    cudaGetSymbolAddress((void**)&wqbf,   g_wqbf);
    cudaGetSymbolAddress((void**)&wpbf,   g_wpbf);

    cudaFuncSetAttribute(gemm_bf16<0>, cudaFuncAttributeMaxDynamicSharedMemorySize, BF_SMEM);
    cudaFuncSetAttribute(gemm_bf16<1>, cudaFuncAttributeMaxDynamicSharedMemorySize, BF_SMEM);
    cudaFuncSetAttribute(gemm_bf16<2>, cudaFuncAttributeMaxDynamicSharedMemorySize, BF_SMEM);
    cudaFuncSetAttribute(gemm_bf16<3>, cudaFuncAttributeMaxDynamicSharedMemorySize, BF_SMEM);

    init_dft_kernel<<<5, 256>>>();
    conv_w_kernel<<<1024, 256>>>(fc1w, fc2w, qkvw, projw);

    // LN1 (+ window partition) -> bf16
    ln_bf16_kernel<<<TOKS, 256>>>(x, n1w, n1b, xlnbf, 1);

    // spatial qkv (bf16 in, fp32 out): 131072 x 768
    gemm_bf16<0><<<dim3(768 / 256, TOKS / 128), 256, BF_SMEM>>>(
        xlnbf, wqbf, qkvb, qkvs, TOKS, 768, 256, nullptr);

    // spectral qkv via DFT of spatial qkv -> bf16
    spec_qkv_kernel<<<dim3(NWIN, 3), 256>>>(qkvs, qkvb, qkvf);

    // attention
    attn_kernel<NTOK, true><<<dim3(NWIN, HEADS), NTOK>>>(qkvs, rpb, attn);
    attn_spec2_kernel<<<dim3(NWIN / 2, HEADS), 160>>>(qkvf, outf);

    // irfft + combine -> bf16 proj input
    ifft_acc_kernel<<<NWIN, 256>>>(outf, attn, attnbf);

    // proj + window reverse + shortcut (bf16 in, fp32 out) -> x2
    gemm_bf16<3><<<dim3(256 / 256, TOKS / 128), 256, BF_SMEM>>>(
        attnbf, wpbf, projb, x2, TOKS, 256, 256, x);

    // LN2 -> bf16
    ln_bf16_kernel<<<TOKS, 256>>>(x2, n2w, n2b, hln, 0);

    // fc1 + GELU (bf16) -> h1 (bf16)
    gemm_bf16<1><<<dim3(1024 / 256, TOKS / 128), 256, BF_SMEM>>>(
        hln, w1bf, fc1b, h1, TOKS, 1024, 256, nullptr);

    // fc2 + residual (bf16 in, fp32 out) -> out
    gemm_bf16<2><<<dim3(256 / 256, TOKS / 128), 256, BF_SMEM>>>(
        h1, w2bf, fc2b, out, TOKS, 256, 1024, x2);
}